// round 6
// baseline (speedup 1.0000x reference)
#include <cuda_runtime.h>
#include <math.h>

// Problem constants (fixed by setup_inputs)
#define BB   2
#define TT   2048
#define CC   1024
#define HH   16
#define HKVV 4
#define DD   64
#define MM   (BB*TT)          // 4096 rows
#define KVD  (HKVV*DD)        // 256

// GEMM tiling
#define BM 128
#define BN 128
#define BK 16

// Attention tiling
#define AQ 128   // query rows per CTA (2 threads per query -> 256 threads)
#define AK 64    // keys per smem tile

// ---------------- scratch (static device globals; no allocs allowed) --------
__device__ float g_q[MM * CC];      // 16 MB
__device__ float g_k[MM * KVD];     // 4 MB
__device__ float g_v[MM * KVD];     // 4 MB
__device__ float g_att[MM * CC];    // 16 MB
__device__ float g_cos[TT][8];
__device__ float g_sin[TT][8];

// ---------------- RoPE table (double precision of fp32 angle) ---------------
__global__ void rope_table_kernel() {
    int idx = blockIdx.x * blockDim.x + threadIdx.x;   // 0 .. TT*8-1
    if (idx >= TT * 8) return;
    int t = idx >> 3;
    int i = idx & 7;
    // inv_freq[i] = 10000^(-(2i)/64), rounded to fp32 like the reference
    double inv_d = exp2(-((double)(2 * i) / 64.0) * 13.28771237954945);  // log2(10000)
    float inv_f = (float)inv_d;
    float ang = (float)t * inv_f;              // fp32 product, like jnp.outer
    g_cos[t][i] = (float)cos((double)ang);
    g_sin[t][i] = (float)sin((double)ang);
}

// ---------------- generic fp32 GEMM tile:  Y = A @ W^T -----------------------
// A row-major [*, K] (stride K), W row-major [N, K] (stride K), Y stride ldy.
__device__ __forceinline__ void gemm_tile(
    const float* __restrict__ A, const float* __restrict__ W,
    float* __restrict__ Y, int ldy, int m0, int n0w, int n0y, int K,
    float (*As)[BM], float (*Bs)[BN])
{
    int tid = threadIdx.x;                 // 0..255
    int tx = tid & 15, ty = tid >> 4;      // 16 x 16 thread grid, 8x8 micro-tile

    float acc[8][8];
#pragma unroll
    for (int i = 0; i < 8; i++)
#pragma unroll
        for (int j = 0; j < 8; j++) acc[i][j] = 0.f;

    int lr = tid >> 1;            // load row 0..127
    int lk = (tid & 1) * 8;       // k offset 0 or 8

    const float* Aptr = A + (size_t)(m0 + lr) * K + lk;
    const float* Wptr = W + (size_t)(n0w + lr) * K + lk;

    for (int k0 = 0; k0 < K; k0 += BK) {
        float4 a0 = *(const float4*)(Aptr + k0);
        float4 a1 = *(const float4*)(Aptr + k0 + 4);
        float4 b0 = *(const float4*)(Wptr + k0);
        float4 b1 = *(const float4*)(Wptr + k0 + 4);
        __syncthreads();
        As[lk+0][lr]=a0.x; As[lk+1][lr]=a0.y; As[lk+2][lr]=a0.z; As[lk+3][lr]=a0.w;
        As[lk+4][lr]=a1.x; As[lk+5][lr]=a1.y; As[lk+6][lr]=a1.z; As[lk+7][lr]=a1.w;
        Bs[lk+0][lr]=b0.x; Bs[lk+1][lr]=b0.y; Bs[lk+2][lr]=b0.z; Bs[lk+3][lr]=b0.w;
        Bs[lk+4][lr]=b1.x; Bs[lk+5][lr]=b1.y; Bs[lk+6][lr]=b1.z; Bs[lk+7][lr]=b1.w;
        __syncthreads();
#pragma unroll
        for (int kk = 0; kk < BK; kk++) {
            float af[8], bf[8];
            *(float4*)(af)     = *(const float4*)&As[kk][ty * 8];
            *(float4*)(af + 4) = *(const float4*)&As[kk][ty * 8 + 4];
            *(float4*)(bf)     = *(const float4*)&Bs[kk][tx * 8];
            *(float4*)(bf + 4) = *(const float4*)&Bs[kk][tx * 8 + 4];
#pragma unroll
            for (int i = 0; i < 8; i++)
#pragma unroll
                for (int j = 0; j < 8; j++) acc[i][j] += af[i] * bf[j];
        }
    }
#pragma unroll
    for (int i = 0; i < 8; i++) {
        float* yr = Y + (size_t)(m0 + ty * 8 + i) * ldy + n0y + tx * 8;
        *(float4*)(yr)     = make_float4(acc[i][0], acc[i][1], acc[i][2], acc[i][3]);
        *(float4*)(yr + 4) = make_float4(acc[i][4], acc[i][5], acc[i][6], acc[i][7]);
    }
}

// Fused QKV GEMM: logical N = 1024 + 256 + 256 = 1536 (12 column tiles)
__global__ __launch_bounds__(256, 2) void qkv_gemm_kernel(
    const float* __restrict__ x, const float* __restrict__ wq,
    const float* __restrict__ wk, const float* __restrict__ wv)
{
    __shared__ float As[BK][BM];
    __shared__ float Bs[BK][BN];
    int n0 = blockIdx.y * BN;
    const float* W; float* Y; int n0w, ldy;
    if (n0 < CC)            { W = wq; Y = g_q; n0w = n0;            ldy = CC;  }
    else if (n0 < CC + KVD) { W = wk; Y = g_k; n0w = n0 - CC;       ldy = KVD; }
    else                    { W = wv; Y = g_v; n0w = n0 - CC - KVD; ldy = KVD; }
    gemm_tile(x, W, Y, ldy, blockIdx.x * BM, n0w, n0w, CC, As, Bs);
}

__global__ __launch_bounds__(256, 2) void proj_gemm_kernel(
    float* __restrict__ out, const float* __restrict__ wproj)
{
    __shared__ float As[BK][BM];
    __shared__ float Bs[BK][BN];
    gemm_tile(g_att, wproj, out, CC, blockIdx.x * BM,
              blockIdx.y * BN, blockIdx.y * BN, CC, As, Bs);
}

// ---------------- RMS norm + partial RoPE (one warp per head vector) --------
__global__ void norm_rope_kernel() {
    int gtid = blockIdx.x * blockDim.x + threadIdx.x;
    int task = gtid >> 5;                     // warp task id
    int lane = gtid & 31;
    const int NTASK = MM * (HH + HKVV);
    if (task >= NTASK) return;
    int row = task / (HH + HKVV);
    int hh  = task % (HH + HKVV);
    float* base = (hh < HH) ? (g_q + (size_t)row * CC + hh * DD)
                            : (g_k + (size_t)row * KVD + (hh - HH) * DD);
    float v0 = base[lane];
    float v1 = base[lane + 32];
    float ss = v0 * v0 + v1 * v1;
#pragma unroll
    for (int o = 16; o; o >>= 1) ss += __shfl_xor_sync(0xffffffffu, ss, o);
    float a = ss * (1.0f / 64.0f) + 1.1920929e-07f;   // eps = finfo(f32).eps
    float r = rsqrtf(a);
    r = r * (1.5f - 0.5f * a * r * r);                // Newton refine
    v0 *= r; v1 *= r;
    // partial RoPE on dims [0,16): pairs (d, d+8)
    int t = row % TT;
    float p = __shfl_xor_sync(0xffffffffu, v0, 8);
    if (lane < 16) {
        int i = lane & 7;
        float c = g_cos[t][i], s = g_sin[t][i];
        v0 = (lane < 8) ? (v0 * c + p * s) : (v0 * c - p * s);
    }
    base[lane] = v0;
    base[lane + 32] = v1;
}

// ---------------- flash attention: 2 threads per query (D split in halves) --
// 256 threads = 128 queries. Pair lanes (2p, 2p+1) hold 32-dim halves of q/o;
// the QK dot is completed with one shfl_xor(.,1). Softmax state (m, l) is
// computed redundantly+identically in both lanes of a pair.
__global__ __launch_bounds__(256, 2) void attn_kernel(
    const float* __restrict__ qgain, const int* __restrict__ wl_ptr)
{
    __shared__ float Ksh[AK][DD];
    __shared__ float Vsh[AK][DD];

    int b  = blockIdx.z;
    int h  = blockIdx.y;
    // reverse order: heavy (high-q0) CTAs launch first -> better 2-wave balance
    int q0 = (gridDim.x - 1 - blockIdx.x) * AQ;
    int tid  = threadIdx.x;
    int p    = tid >> 1;              // query slot 0..127
    int half = tid & 1;               // which 32-dim half
    int hoff = half * 32;
    int kvh  = h >> 2;
    int qi   = q0 + p;
    int row  = b * TT + qi;

    // warp-uniform query bounds (warp w owns queries 16w .. 16w+15)
    int warp = tid >> 5;
    int qi_wmin = q0 + warp * 16;
    int qi_wmax = qi_wmin + 15;

    int wl = *wl_ptr;
    if (wl < 0) wl = TT;              // no window

    // fold gain * 1/sqrt(D) * log2(e) into q  -> softmax in exp2 domain
    float qscale = qgain[h] * 0.125f * 1.4426950408889634f;

    float q[32];
    {
        const float* qp = g_q + (size_t)row * CC + h * DD + hoff;
#pragma unroll
        for (int d = 0; d < 32; d += 4) {
            float4 t4 = *(const float4*)(qp + d);
            q[d] = t4.x * qscale; q[d+1] = t4.y * qscale;
            q[d+2] = t4.z * qscale; q[d+3] = t4.w * qscale;
        }
    }
    float o[32];
#pragma unroll
    for (int d = 0; d < 32; d++) o[d] = 0.f;
    float mrun = -INFINITY, lrun = 0.f;

    int lo = q0 - wl;
    int kt_lo = (lo > 0) ? (lo / AK) : 0;
    int kt_hi = (q0 + AQ - 1) / AK;          // inclusive

    const float* kbase = g_k + (size_t)b * TT * KVD + kvh * DD;
    const float* vbase = g_v + (size_t)b * TT * KVD + kvh * DD;

    // tile-load mapping: 4 threads per row, 16 floats each
    int lrow = tid >> 2;
    int lseg = (tid & 3) * 16;

#pragma unroll 1
    for (int kt = kt_lo; kt <= kt_hi; kt++) {
        int k0 = kt * AK;
        __syncthreads();
        {
            const float* kr = kbase + (size_t)(k0 + lrow) * KVD + lseg;
            const float* vr = vbase + (size_t)(k0 + lrow) * KVD + lseg;
#pragma unroll
            for (int j = 0; j < 16; j += 4) {
                *(float4*)&Ksh[lrow][lseg + j] = *(const float4*)(kr + j);
                *(float4*)&Vsh[lrow][lseg + j] = *(const float4*)(vr + j);
            }
        }
        __syncthreads();

#pragma unroll 1
        for (int c = 0; c < AK; c += 8) {
            if (k0 + c > qi_wmax) break;               // warp-uniform: no live keys left
            if (k0 + c + 8 <= qi_wmin - wl) continue;  // warp-uniform: all behind window

            // half-dot partials for 8 keys
            float s[8];
#pragma unroll
            for (int j = 0; j < 8; j++) {
                float acc = 0.f;
#pragma unroll
                for (int d = 0; d < 32; d += 4) {
                    float4 k4 = *(const float4*)&Ksh[c + j][hoff + d];
                    acc += q[d] * k4.x + q[d+1] * k4.y
                         + q[d+2] * k4.z + q[d+3] * k4.w;
                }
                s[j] = acc;
            }
            // complete the dot across the pair (warp-convergent here)
#pragma unroll
            for (int j = 0; j < 8; j++)
                s[j] += __shfl_xor_sync(0xffffffffu, s[j], 1);
            // mask
#pragma unroll
            for (int j = 0; j < 8; j++) {
                int kj = k0 + c + j;
                bool ok = (kj <= qi) && (qi - kj <= wl);
                if (!ok) s[j] = -INFINITY;
            }
            float mc = s[0];
#pragma unroll
            for (int j = 1; j < 8; j++) mc = fmaxf(mc, s[j]);
            if (mc == -INFINITY) continue;   // this query sees nothing in chunk
            float mnew = fmaxf(mrun, mc);
            float corr = exp2f(mrun - mnew); // mrun=-inf -> 0, correct
            lrun *= corr;
#pragma unroll
            for (int d = 0; d < 32; d++) o[d] *= corr;
#pragma unroll
            for (int j = 0; j < 8; j++) {
                s[j] = exp2f(s[j] - mnew);   // masked -> exp2(-inf) = 0
                lrun += s[j];
            }
#pragma unroll
            for (int j = 0; j < 8; j++) {
#pragma unroll
                for (int d = 0; d < 32; d += 4) {
                    float4 v4 = *(const float4*)&Vsh[c + j][hoff + d];
                    o[d]   += s[j] * v4.x; o[d+1] += s[j] * v4.y;
                    o[d+2] += s[j] * v4.z; o[d+3] += s[j] * v4.w;
                }
            }
            mrun = mnew;
        }
    }

    float inv = 1.0f / lrun;
    float* op = g_att + (size_t)row * CC + h * DD + hoff;
#pragma unroll
    for (int d = 0; d < 32; d += 4) {
        *(float4*)(op + d) = make_float4(o[d]*inv, o[d+1]*inv, o[d+2]*inv, o[d+3]*inv);
    }
}

// ---------------- launch -----------------------------------------------------
extern "C" void kernel_launch(void* const* d_in, const int* in_sizes, int n_in,
                              void* d_out, int out_size) {
    const float* x     = (const float*)d_in[0];
    const float* wq    = (const float*)d_in[1];
    const float* wk    = (const float*)d_in[2];
    const float* wv    = (const float*)d_in[3];
    const float* wproj = (const float*)d_in[4];
    const float* qgain = (const float*)d_in[5];
    const int*   wl    = (const int*)d_in[6];
    float* out = (float*)d_out;

    rope_table_kernel<<<(TT * 8 + 255) / 256, 256>>>();

    dim3 g1(MM / BM, (CC + 2 * KVD) / BN);   // 32 x 12
    qkv_gemm_kernel<<<g1, 256>>>(x, wq, wk, wv);

    int ntask = MM * (HH + HKVV);
    norm_rope_kernel<<<(ntask * 32 + 255) / 256, 256>>>();

    dim3 g2(TT / AQ, HH, BB);                // 16 x 16 x 2
    attn_kernel<<<g2, 256>>>(qgain, wl);

    dim3 g3(MM / BM, CC / BN);               // 32 x 8
    proj_gemm_kernel<<<g3, 256>>>(out, wproj);
}

// round 7
// speedup vs baseline: 1.5457x; 1.5457x over previous
#include <cuda_runtime.h>
#include <math.h>

// Problem constants (fixed by setup_inputs)
#define BB   2
#define TT   2048
#define CC   1024
#define HH   16
#define HKVV 4
#define DD   64
#define MM   (BB*TT)          // 4096 rows
#define KVD  (HKVV*DD)        // 256

// GEMM tiling
#define BM 128
#define BN 128
#define BK 16

// Attention tiling: 128 queries x 64-key tiles, 256 threads, 8x4 micro-tiles
#define AQ 128
#define AK 64

// ---------------- scratch (static device globals; no allocs allowed) --------
__device__ float g_q[MM * CC];      // 16 MB
__device__ float g_k[MM * KVD];     // 4 MB
__device__ float g_v[MM * KVD];     // 4 MB
__device__ float g_att[MM * CC];    // 16 MB
__device__ float g_cos[TT][8];
__device__ float g_sin[TT][8];

// ---------------- RoPE table (double precision of fp32 angle) ---------------
__global__ void rope_table_kernel() {
    int idx = blockIdx.x * blockDim.x + threadIdx.x;   // 0 .. TT*8-1
    if (idx >= TT * 8) return;
    int t = idx >> 3;
    int i = idx & 7;
    double inv_d = exp2(-((double)(2 * i) / 64.0) * 13.28771237954945);  // log2(10000)
    float inv_f = (float)inv_d;
    float ang = (float)t * inv_f;              // fp32 product, like jnp.outer
    g_cos[t][i] = (float)cos((double)ang);
    g_sin[t][i] = (float)sin((double)ang);
}

// ---------------- generic fp32 GEMM tile:  Y = A @ W^T -----------------------
__device__ __forceinline__ void gemm_tile(
    const float* __restrict__ A, const float* __restrict__ W,
    float* __restrict__ Y, int ldy, int m0, int n0w, int n0y, int K,
    float (*As)[BM], float (*Bs)[BN])
{
    int tid = threadIdx.x;
    int tx = tid & 15, ty = tid >> 4;

    float acc[8][8];
#pragma unroll
    for (int i = 0; i < 8; i++)
#pragma unroll
        for (int j = 0; j < 8; j++) acc[i][j] = 0.f;

    int lr = tid >> 1;
    int lk = (tid & 1) * 8;

    const float* Aptr = A + (size_t)(m0 + lr) * K + lk;
    const float* Wptr = W + (size_t)(n0w + lr) * K + lk;

    for (int k0 = 0; k0 < K; k0 += BK) {
        float4 a0 = *(const float4*)(Aptr + k0);
        float4 a1 = *(const float4*)(Aptr + k0 + 4);
        float4 b0 = *(const float4*)(Wptr + k0);
        float4 b1 = *(const float4*)(Wptr + k0 + 4);
        __syncthreads();
        As[lk+0][lr]=a0.x; As[lk+1][lr]=a0.y; As[lk+2][lr]=a0.z; As[lk+3][lr]=a0.w;
        As[lk+4][lr]=a1.x; As[lk+5][lr]=a1.y; As[lk+6][lr]=a1.z; As[lk+7][lr]=a1.w;
        Bs[lk+0][lr]=b0.x; Bs[lk+1][lr]=b0.y; Bs[lk+2][lr]=b0.z; Bs[lk+3][lr]=b0.w;
        Bs[lk+4][lr]=b1.x; Bs[lk+5][lr]=b1.y; Bs[lk+6][lr]=b1.z; Bs[lk+7][lr]=b1.w;
        __syncthreads();
#pragma unroll
        for (int kk = 0; kk < BK; kk++) {
            float af[8], bf[8];
            *(float4*)(af)     = *(const float4*)&As[kk][ty * 8];
            *(float4*)(af + 4) = *(const float4*)&As[kk][ty * 8 + 4];
            *(float4*)(bf)     = *(const float4*)&Bs[kk][tx * 8];
            *(float4*)(bf + 4) = *(const float4*)&Bs[kk][tx * 8 + 4];
#pragma unroll
            for (int i = 0; i < 8; i++)
#pragma unroll
                for (int j = 0; j < 8; j++) acc[i][j] += af[i] * bf[j];
        }
    }
#pragma unroll
    for (int i = 0; i < 8; i++) {
        float* yr = Y + (size_t)(m0 + ty * 8 + i) * ldy + n0y + tx * 8;
        *(float4*)(yr)     = make_float4(acc[i][0], acc[i][1], acc[i][2], acc[i][3]);
        *(float4*)(yr + 4) = make_float4(acc[i][4], acc[i][5], acc[i][6], acc[i][7]);
    }
}

__global__ __launch_bounds__(256, 2) void qkv_gemm_kernel(
    const float* __restrict__ x, const float* __restrict__ wq,
    const float* __restrict__ wk, const float* __restrict__ wv)
{
    __shared__ float As[BK][BM];
    __shared__ float Bs[BK][BN];
    int n0 = blockIdx.y * BN;
    const float* W; float* Y; int n0w, ldy;
    if (n0 < CC)            { W = wq; Y = g_q; n0w = n0;            ldy = CC;  }
    else if (n0 < CC + KVD) { W = wk; Y = g_k; n0w = n0 - CC;       ldy = KVD; }
    else                    { W = wv; Y = g_v; n0w = n0 - CC - KVD; ldy = KVD; }
    gemm_tile(x, W, Y, ldy, blockIdx.x * BM, n0w, n0w, CC, As, Bs);
}

__global__ __launch_bounds__(256, 2) void proj_gemm_kernel(
    float* __restrict__ out, const float* __restrict__ wproj)
{
    __shared__ float As[BK][BM];
    __shared__ float Bs[BK][BN];
    gemm_tile(g_att, wproj, out, CC, blockIdx.x * BM,
              blockIdx.y * BN, blockIdx.y * BN, CC, As, Bs);
}

// ---------------- RMS norm + partial RoPE (one warp per head vector) --------
__global__ void norm_rope_kernel() {
    int gtid = blockIdx.x * blockDim.x + threadIdx.x;
    int task = gtid >> 5;
    int lane = gtid & 31;
    const int NTASK = MM * (HH + HKVV);
    if (task >= NTASK) return;
    int row = task / (HH + HKVV);
    int hh  = task % (HH + HKVV);
    float* base = (hh < HH) ? (g_q + (size_t)row * CC + hh * DD)
                            : (g_k + (size_t)row * KVD + (hh - HH) * DD);
    float v0 = base[lane];
    float v1 = base[lane + 32];
    float ss = v0 * v0 + v1 * v1;
#pragma unroll
    for (int o = 16; o; o >>= 1) ss += __shfl_xor_sync(0xffffffffu, ss, o);
    float a = ss * (1.0f / 64.0f) + 1.1920929e-07f;
    float r = rsqrtf(a);
    r = r * (1.5f - 0.5f * a * r * r);
    v0 *= r; v1 *= r;
    int t = row % TT;
    float p = __shfl_xor_sync(0xffffffffu, v0, 8);
    if (lane < 16) {
        int i = lane & 7;
        float c = g_cos[t][i], s = g_sin[t][i];
        v0 = (lane < 8) ? (v0 * c + p * s) : (v0 * c - p * s);
    }
    base[lane] = v0;
    base[lane + 32] = v1;
}

// ---------------- flash attention: register-tiled GEMM structure ------------
// 256 threads, tx=tid&15 (keys/dims), ty=tid>>4 (queries). Micro-tiles 8x4.
// smem (dynamic, 96 KB): Qs[64][128] dim-major, Ks[64][64] dim-major,
//                        Vs[64][64] key-major, Ps[64][128] key-major.
#define QS_OFF 0
#define KS_OFF 8192
#define VS_OFF 12288
#define PS_OFF 16384
#define ATTN_SMEM_BYTES (24576 * 4)

__global__ __launch_bounds__(256, 2) void attn_kernel(
    const float* __restrict__ qgain, const int* __restrict__ wl_ptr)
{
    extern __shared__ float sm[];
    float* Qs = sm + QS_OFF;   // [d][q]  64 x 128
    float* Ks = sm + KS_OFF;   // [d][k]  64 x 64
    float* Vs = sm + VS_OFF;   // [k][d]  64 x 64
    float* Ps = sm + PS_OFF;   // [k][q]  64 x 128

    int tid = threadIdx.x;
    int tx = tid & 15, ty = tid >> 4;
    int h  = blockIdx.x & 15;
    int b  = blockIdx.x >> 4;
    int q0 = (int)(gridDim.y - 1 - blockIdx.y) * AQ;   // heavy CTAs first
    int kvh = h >> 2;

    int wl = *wl_ptr;
    if (wl < 0) wl = TT;

    float qscale = qgain[h] * 0.125f * 1.4426950408889634f;  // gain/sqrt(D)*log2e

    // ---- load Q tile transposed into Qs[d][q], scaled ----
    {
        int qloc = tid >> 1;
        int dseg = (tid & 1) * 32;
        const float* qp = g_q + (size_t)(b * TT + q0 + qloc) * CC + h * DD + dseg;
#pragma unroll
        for (int v = 0; v < 8; v++) {
            float4 t4 = *(const float4*)(qp + v * 4);
            Qs[(dseg + v*4 + 0) * AQ + qloc] = t4.x * qscale;
            Qs[(dseg + v*4 + 1) * AQ + qloc] = t4.y * qscale;
            Qs[(dseg + v*4 + 2) * AQ + qloc] = t4.z * qscale;
            Qs[(dseg + v*4 + 3) * AQ + qloc] = t4.w * qscale;
        }
    }

    float O[8][4];
#pragma unroll
    for (int i = 0; i < 8; i++)
#pragma unroll
        for (int j = 0; j < 4; j++) O[i][j] = 0.f;
    float m[8], l[8];
#pragma unroll
    for (int i = 0; i < 8; i++) { m[i] = -INFINITY; l[i] = 0.f; }

    int lo = q0 - wl;
    int kt_lo = (lo > 0) ? (lo / AK) : 0;
    int kt_hi = (q0 + AQ - 1) / AK;

    const float* kbase = g_k + (size_t)b * TT * KVD + kvh * DD;
    const float* vbase = g_v + (size_t)b * TT * KVD + kvh * DD;

    unsigned gmask = 0xFFFFu << (tid & 16);   // 16-lane row group mask

    int kloc = tid >> 2;
    int dsg  = (tid & 3) * 16;

#pragma unroll 1
    for (int kt = kt_lo; kt <= kt_hi; kt++) {
        int k0 = kt * AK;
        __syncthreads();   // previous PV (Vs/Ps reads) done before overwrite
        // ---- load K transposed -> Ks[d][k]; V straight -> Vs[k][d] ----
        {
            const float* kr = kbase + (size_t)(k0 + kloc) * KVD + dsg;
            const float* vr = vbase + (size_t)(k0 + kloc) * KVD + dsg;
#pragma unroll
            for (int v = 0; v < 4; v++) {
                float4 kk = *(const float4*)(kr + v * 4);
                Ks[(dsg + v*4 + 0) * AK + kloc] = kk.x;
                Ks[(dsg + v*4 + 1) * AK + kloc] = kk.y;
                Ks[(dsg + v*4 + 2) * AK + kloc] = kk.z;
                Ks[(dsg + v*4 + 3) * AK + kloc] = kk.w;
                *(float4*)&Vs[kloc * AK + dsg + v*4] = *(const float4*)(vr + v * 4);
            }
        }
        __syncthreads();

        // ---- QK^T: s[8q][4k], K-loop over 64 dims ----
        float s[8][4];
#pragma unroll
        for (int i = 0; i < 8; i++)
#pragma unroll
            for (int j = 0; j < 4; j++) s[i][j] = 0.f;

#pragma unroll 8
        for (int d = 0; d < 64; d++) {
            float4 kf = *(const float4*)&Ks[d * AK + tx * 4];
            float4 qa = *(const float4*)&Qs[d * AQ + ty * 8];
            float4 qb = *(const float4*)&Qs[d * AQ + ty * 8 + 4];
            float qf[8] = {qa.x, qa.y, qa.z, qa.w, qb.x, qb.y, qb.z, qb.w};
#pragma unroll
            for (int i = 0; i < 8; i++) {
                s[i][0] += qf[i] * kf.x;
                s[i][1] += qf[i] * kf.y;
                s[i][2] += qf[i] * kf.z;
                s[i][3] += qf[i] * kf.w;
            }
        }

        // ---- mask + online softmax (row groups = 16 tx threads) ----
#pragma unroll
        for (int i = 0; i < 8; i++) {
            int qg = q0 + ty * 8 + i;
#pragma unroll
            for (int j = 0; j < 4; j++) {
                int kj = k0 + tx * 4 + j;
                bool ok = (kj <= qg) && (qg - kj <= wl);
                if (!ok) s[i][j] = -INFINITY;
            }
            float mc = fmaxf(fmaxf(s[i][0], s[i][1]), fmaxf(s[i][2], s[i][3]));
            mc = fmaxf(mc, __shfl_xor_sync(gmask, mc, 1));
            mc = fmaxf(mc, __shfl_xor_sync(gmask, mc, 2));
            mc = fmaxf(mc, __shfl_xor_sync(gmask, mc, 4));
            mc = fmaxf(mc, __shfl_xor_sync(gmask, mc, 8));
            if (mc == -INFINITY) {
                s[i][0] = s[i][1] = s[i][2] = s[i][3] = 0.f;  // zero P row
            } else {
                float mnew = fmaxf(m[i], mc);
                float corr = exp2f(m[i] - mnew);   // m=-inf -> 0
                l[i] *= corr;
                O[i][0] *= corr; O[i][1] *= corr; O[i][2] *= corr; O[i][3] *= corr;
                float sum = 0.f;
#pragma unroll
                for (int j = 0; j < 4; j++) {
                    s[i][j] = exp2f(s[i][j] - mnew);
                    sum += s[i][j];
                }
                sum += __shfl_xor_sync(gmask, sum, 1);
                sum += __shfl_xor_sync(gmask, sum, 2);
                sum += __shfl_xor_sync(gmask, sum, 4);
                sum += __shfl_xor_sync(gmask, sum, 8);
                l[i] += sum;
                m[i] = mnew;
            }
        }

        __syncthreads();   // (cheap; orders nothing harmful, keeps P write race-free vs QK reads elsewhere)
        // ---- write P tile: Ps[k][q] ----
#pragma unroll
        for (int j = 0; j < 4; j++) {
            float* pr = &Ps[(tx * 4 + j) * AQ + ty * 8];
            *(float4*)(pr)     = make_float4(s[0][j], s[1][j], s[2][j], s[3][j]);
            *(float4*)(pr + 4) = make_float4(s[4][j], s[5][j], s[6][j], s[7][j]);
        }
        __syncthreads();

        // ---- P @ V: K-loop over 64 keys, O[8q][4d] ----
#pragma unroll 8
        for (int k = 0; k < 64; k++) {
            float4 vf = *(const float4*)&Vs[k * AK + tx * 4];
            float4 pa = *(const float4*)&Ps[k * AQ + ty * 8];
            float4 pb = *(const float4*)&Ps[k * AQ + ty * 8 + 4];
            float pf[8] = {pa.x, pa.y, pa.z, pa.w, pb.x, pb.y, pb.z, pb.w};
#pragma unroll
            for (int i = 0; i < 8; i++) {
                O[i][0] += pf[i] * vf.x;
                O[i][1] += pf[i] * vf.y;
                O[i][2] += pf[i] * vf.z;
                O[i][3] += pf[i] * vf.w;
            }
        }
    }

    // ---- epilogue: O / l ----
#pragma unroll
    for (int i = 0; i < 8; i++) {
        float inv = 1.0f / l[i];
        float* op = g_att + (size_t)(b * TT + q0 + ty * 8 + i) * CC + h * DD + tx * 4;
        *(float4*)op = make_float4(O[i][0]*inv, O[i][1]*inv, O[i][2]*inv, O[i][3]*inv);
    }
}

// ---------------- launch -----------------------------------------------------
extern "C" void kernel_launch(void* const* d_in, const int* in_sizes, int n_in,
                              void* d_out, int out_size) {
    const float* x     = (const float*)d_in[0];
    const float* wq    = (const float*)d_in[1];
    const float* wk    = (const float*)d_in[2];
    const float* wv    = (const float*)d_in[3];
    const float* wproj = (const float*)d_in[4];
    const float* qgain = (const float*)d_in[5];
    const int*   wl    = (const int*)d_in[6];
    float* out = (float*)d_out;

    cudaFuncSetAttribute(attn_kernel,
                         cudaFuncAttributeMaxDynamicSharedMemorySize,
                         ATTN_SMEM_BYTES);

    rope_table_kernel<<<(TT * 8 + 255) / 256, 256>>>();

    dim3 g1(MM / BM, (CC + 2 * KVD) / BN);   // 32 x 12
    qkv_gemm_kernel<<<g1, 256>>>(x, wq, wk, wv);

    int ntask = MM * (HH + HKVV);
    norm_rope_kernel<<<(ntask * 32 + 255) / 256, 256>>>();

    dim3 g2(HH * BB, TT / AQ);               // 32 x 16, y = q-tile (reversed inside)
    attn_kernel<<<g2, 256, ATTN_SMEM_BYTES>>>(qgain, wl);

    dim3 g3(MM / BM, CC / BN);               // 32 x 8
    proj_gemm_kernel<<<g3, 256>>>(out, wproj);
}

// round 9
// speedup vs baseline: 1.9038x; 1.2316x over previous
#include <cuda_runtime.h>
#include <cuda_bf16.h>
#include <math.h>
#include <cstdint>

// Problem constants (fixed by setup_inputs)
#define BB   2
#define TT   2048
#define CC   1024
#define HH   16
#define HKVV 4
#define DD   64
#define MM   (BB*TT)          // 4096 rows
#define KVD  (HKVV*DD)        // 256

// Attention tiling
#define AQ 128
#define AK 64

// GEMM (mma.sync) tiling
#define KC   32               // fp32 K elements per chunk
#define NCH  (CC / KC)        // 32 chunks
#define SP   40               // smem row stride in bf16 elems (conflict-free)
#define BUFE (4 * 128 * SP)   // elems per buffer (4 arrays)
#define AHO  0
#define ALO  (128 * SP)
#define BHO  (2 * 128 * SP)
#define BLO  (3 * 128 * SP)
#define GEMM_SMEM_BYTES (2 * BUFE * 2)   // 81920 bytes

// ---------------- scratch (static device globals; no allocs allowed) --------
__device__ float g_q[MM * CC];      // 16 MB
__device__ float g_k[MM * KVD];     // 4 MB
__device__ float g_v[MM * KVD];     // 4 MB
__device__ float g_att[MM * CC];    // 16 MB
__device__ float g_cos[TT][8];
__device__ float g_sin[TT][8];

// ---------------- warp-level bf16 MMA (baseline PTX, valid on compute_100) --
__device__ __forceinline__ void mma_bf16(
    float* c, uint32_t a0, uint32_t a1, uint32_t a2, uint32_t a3,
    uint32_t b0, uint32_t b1)
{
    asm volatile(
        "mma.sync.aligned.m16n8k16.row.col.f32.bf16.bf16.f32 "
        "{%0,%1,%2,%3}, {%4,%5,%6,%7}, {%8,%9}, {%0,%1,%2,%3};"
        : "+f"(c[0]), "+f"(c[1]), "+f"(c[2]), "+f"(c[3])
        : "r"(a0), "r"(a1), "r"(a2), "r"(a3), "r"(b0), "r"(b1));
}

__device__ __forceinline__ uint32_t lds_b32(const __nv_bfloat16* p) {
    return *(const uint32_t*)p;
}

// convert 16 fp32 (4 float4) -> hi/lo bf16 rows in smem
__device__ __forceinline__ void cvt_store16(
    __nv_bfloat16* hi, __nv_bfloat16* lo, uint32_t base, const float4* p)
{
#pragma unroll
    for (int j = 0; j < 4; j++) {
        float4 v = p[j];
        __nv_bfloat16 hx = __float2bfloat16_rn(v.x), hy = __float2bfloat16_rn(v.y);
        __nv_bfloat16 hz = __float2bfloat16_rn(v.z), hw = __float2bfloat16_rn(v.w);
        *(__nv_bfloat162*)(hi + base + j*4)     = __halves2bfloat162(hx, hy);
        *(__nv_bfloat162*)(hi + base + j*4 + 2) = __halves2bfloat162(hz, hw);
        *(__nv_bfloat162*)(lo + base + j*4) =
            __floats2bfloat162_rn(v.x - __bfloat162float(hx),
                                  v.y - __bfloat162float(hy));
        *(__nv_bfloat162*)(lo + base + j*4 + 2) =
            __floats2bfloat162_rn(v.z - __bfloat162float(hz),
                                  v.w - __bfloat162float(hw));
    }
}

// one k16 step: 4 m-frags x 4 n-frags x 3 split MMAs
__device__ __forceinline__ void gemm_compute_k16(
    const __nv_bfloat16* ah, const __nv_bfloat16* al,
    const __nv_bfloat16* bh, const __nv_bfloat16* bl,
    int mbase, int nbase, int g, int tg, int kk, float* acc)
{
    uint32_t bfh[8], bfl[8];
#pragma unroll
    for (int j = 0; j < 4; j++) {
        int r = (nbase + j*8 + g) * SP + kk + tg*2;
        bfh[2*j]   = lds_b32(bh + r);
        bfh[2*j+1] = lds_b32(bh + r + 8);
        bfl[2*j]   = lds_b32(bl + r);
        bfl[2*j+1] = lds_b32(bl + r + 8);
    }
#pragma unroll
    for (int i = 0; i < 4; i++) {
        int r0 = (mbase + i*16 + g) * SP + kk + tg*2;
        int r1 = r0 + 8 * SP;
        uint32_t a0 = lds_b32(ah + r0),     a1 = lds_b32(ah + r1);
        uint32_t a2 = lds_b32(ah + r0 + 8), a3 = lds_b32(ah + r1 + 8);
        uint32_t l0 = lds_b32(al + r0),     l1 = lds_b32(al + r1);
        uint32_t l2 = lds_b32(al + r0 + 8), l3 = lds_b32(al + r1 + 8);
#pragma unroll
        for (int j = 0; j < 4; j++) {
            float* c = acc + (i*4 + j) * 4;
            mma_bf16(c, a0, a1, a2, a3, bfh[2*j], bfh[2*j+1]);
            mma_bf16(c, a0, a1, a2, a3, bfl[2*j], bfl[2*j+1]);
            mma_bf16(c, l0, l1, l2, l3, bfh[2*j], bfh[2*j+1]);
        }
    }
}

// Y[128x128 tile] = A[128,1024] @ W[128,1024]^T, bf16-split on tensor pipe
__device__ __forceinline__ void mma_gemm_body(
    const float* __restrict__ A, const float* __restrict__ W,
    float* __restrict__ Y, int ldy, int m0, int n0w, int n0y)
{
    extern __shared__ __nv_bfloat16 gsm[];

    int tid = threadIdx.x, wid = tid >> 5, lane = tid & 31;
    int g = lane >> 2, tg = lane & 3;
    int mbase = (wid & 1) * 64;
    int nbase = (wid >> 1) * 32;

    int lrow  = tid >> 1;
    int lhalf = (tid & 1) * 16;
    const float* gA = A + (size_t)(m0  + lrow) * CC + lhalf;
    const float* gW = W + (size_t)(n0w + lrow) * CC + lhalf;
    uint32_t sbase = lrow * SP + lhalf;

    float acc[64];
#pragma unroll
    for (int i = 0; i < 64; i++) acc[i] = 0.f;

    float4 pa[4], pw[4];
#pragma unroll
    for (int j = 0; j < 4; j++) {
        pa[j] = *(const float4*)(gA + j*4);
        pw[j] = *(const float4*)(gW + j*4);
    }
    cvt_store16(gsm + AHO, gsm + ALO, sbase, pa);
    cvt_store16(gsm + BHO, gsm + BLO, sbase, pw);
    __syncthreads();

#pragma unroll 1
    for (int ch = 0; ch < NCH; ch++) {
        __nv_bfloat16* cur = gsm + (ch & 1) * BUFE;
        __nv_bfloat16* nxt = gsm + ((ch + 1) & 1) * BUFE;
        if (ch < NCH - 1) {
            int kc = (ch + 1) * KC;
#pragma unroll
            for (int j = 0; j < 4; j++) {
                pa[j] = *(const float4*)(gA + kc + j*4);
                pw[j] = *(const float4*)(gW + kc + j*4);
            }
        }
        gemm_compute_k16(cur + AHO, cur + ALO, cur + BHO, cur + BLO,
                         mbase, nbase, g, tg, 0, acc);
        gemm_compute_k16(cur + AHO, cur + ALO, cur + BHO, cur + BLO,
                         mbase, nbase, g, tg, 16, acc);
        if (ch < NCH - 1) {
            cvt_store16(nxt + AHO, nxt + ALO, sbase, pa);
            cvt_store16(nxt + BHO, nxt + BLO, sbase, pw);
        }
        __syncthreads();
    }

    // epilogue: D frag -> Y (float2 per row pair)
#pragma unroll
    for (int i = 0; i < 4; i++) {
#pragma unroll
        for (int j = 0; j < 4; j++) {
            float* c = acc + (i*4 + j) * 4;
            int mrow = m0  + mbase + i*16 + g;
            int ncol = n0y + nbase + j*8 + tg*2;
            *(float2*)&Y[(size_t)mrow * ldy + ncol]       = make_float2(c[0], c[1]);
            *(float2*)&Y[(size_t)(mrow + 8) * ldy + ncol] = make_float2(c[2], c[3]);
        }
    }
}

// Fused QKV GEMM: logical N = 1024 + 256 + 256 = 1536 (12 column tiles)
__global__ __launch_bounds__(256, 1) void qkv_gemm_kernel(
    const float* __restrict__ x, const float* __restrict__ wq,
    const float* __restrict__ wk, const float* __restrict__ wv)
{
    int n0 = blockIdx.y * 128;
    const float* W; float* Y; int n0w, ldy;
    if (n0 < CC)            { W = wq; Y = g_q; n0w = n0;            ldy = CC;  }
    else if (n0 < CC + KVD) { W = wk; Y = g_k; n0w = n0 - CC;       ldy = KVD; }
    else                    { W = wv; Y = g_v; n0w = n0 - CC - KVD; ldy = KVD; }
    mma_gemm_body(x, W, Y, ldy, blockIdx.x * 128, n0w, n0w);
}

__global__ __launch_bounds__(256, 1) void proj_gemm_kernel(
    float* __restrict__ out, const float* __restrict__ wproj)
{
    mma_gemm_body(g_att, wproj, out, CC, blockIdx.x * 128,
                  blockIdx.y * 128, blockIdx.y * 128);
}

// ---------------- RoPE table (double precision of fp32 angle) ---------------
__global__ void rope_table_kernel() {
    int idx = blockIdx.x * blockDim.x + threadIdx.x;   // 0 .. TT*8-1
    if (idx >= TT * 8) return;
    int t = idx >> 3;
    int i = idx & 7;
    double inv_d = exp2(-((double)(2 * i) / 64.0) * 13.28771237954945);  // log2(10000)
    float inv_f = (float)inv_d;
    float ang = (float)t * inv_f;              // fp32 product, like jnp.outer
    g_cos[t][i] = (float)cos((double)ang);
    g_sin[t][i] = (float)sin((double)ang);
}

// ---------------- RMS norm + partial RoPE (one warp per head vector) --------
__global__ void norm_rope_kernel() {
    int gtid = blockIdx.x * blockDim.x + threadIdx.x;
    int task = gtid >> 5;
    int lane = gtid & 31;
    const int NTASK = MM * (HH + HKVV);
    if (task >= NTASK) return;
    int row = task / (HH + HKVV);
    int hh  = task % (HH + HKVV);
    float* base = (hh < HH) ? (g_q + (size_t)row * CC + hh * DD)
                            : (g_k + (size_t)row * KVD + (hh - HH) * DD);
    float v0 = base[lane];
    float v1 = base[lane + 32];
    float ss = v0 * v0 + v1 * v1;
#pragma unroll
    for (int o = 16; o; o >>= 1) ss += __shfl_xor_sync(0xffffffffu, ss, o);
    float a = ss * (1.0f / 64.0f) + 1.1920929e-07f;
    float r = rsqrtf(a);
    r = r * (1.5f - 0.5f * a * r * r);
    v0 *= r; v1 *= r;
    int t = row % TT;
    float p = __shfl_xor_sync(0xffffffffu, v0, 8);
    if (lane < 16) {
        int i = lane & 7;
        float c = g_cos[t][i], s = g_sin[t][i];
        v0 = (lane < 8) ? (v0 * c + p * s) : (v0 * c - p * s);
    }
    base[lane] = v0;
    base[lane + 32] = v1;
}

// ---------------- flash attention: register-tiled GEMM structure ------------
#define QS_OFF 0
#define KS_OFF 8192
#define VS_OFF 12288
#define PS_OFF 16384
#define ATTN_SMEM_BYTES (24576 * 4)

__global__ __launch_bounds__(256, 2) void attn_kernel(
    const float* __restrict__ qgain, const int* __restrict__ wl_ptr)
{
    extern __shared__ float sm[];
    float* Qs = sm + QS_OFF;   // [d][q]  64 x 128
    float* Ks = sm + KS_OFF;   // [d][k]  64 x 64
    float* Vs = sm + VS_OFF;   // [k][d]  64 x 64
    float* Ps = sm + PS_OFF;   // [k][q]  64 x 128

    int tid = threadIdx.x;
    int tx = tid & 15, ty = tid >> 4;
    int h  = blockIdx.x & 15;
    int b  = blockIdx.x >> 4;
    int q0 = (int)(gridDim.y - 1 - blockIdx.y) * AQ;   // heavy CTAs first
    int kvh = h >> 2;

    int wl = *wl_ptr;
    if (wl < 0) wl = TT;

    float qscale = qgain[h] * 0.125f * 1.4426950408889634f;  // gain/sqrt(D)*log2e

    {
        int qloc = tid >> 1;
        int dseg = (tid & 1) * 32;
        const float* qp = g_q + (size_t)(b * TT + q0 + qloc) * CC + h * DD + dseg;
#pragma unroll
        for (int v = 0; v < 8; v++) {
            float4 t4 = *(const float4*)(qp + v * 4);
            Qs[(dseg + v*4 + 0) * AQ + qloc] = t4.x * qscale;
            Qs[(dseg + v*4 + 1) * AQ + qloc] = t4.y * qscale;
            Qs[(dseg + v*4 + 2) * AQ + qloc] = t4.z * qscale;
            Qs[(dseg + v*4 + 3) * AQ + qloc] = t4.w * qscale;
        }
    }

    float O[8][4];
#pragma unroll
    for (int i = 0; i < 8; i++)
#pragma unroll
        for (int j = 0; j < 4; j++) O[i][j] = 0.f;
    float m[8], l[8];
#pragma unroll
    for (int i = 0; i < 8; i++) { m[i] = -INFINITY; l[i] = 0.f; }

    int lo = q0 - wl;
    int kt_lo = (lo > 0) ? (lo / AK) : 0;
    int kt_hi = (q0 + AQ - 1) / AK;

    const float* kbase = g_k + (size_t)b * TT * KVD + kvh * DD;
    const float* vbase = g_v + (size_t)b * TT * KVD + kvh * DD;

    unsigned gmask = 0xFFFFu << (tid & 16);

    int kloc = tid >> 2;
    int dsg  = (tid & 3) * 16;

#pragma unroll 1
    for (int kt = kt_lo; kt <= kt_hi; kt++) {
        int k0 = kt * AK;
        __syncthreads();
        {
            const float* kr = kbase + (size_t)(k0 + kloc) * KVD + dsg;
            const float* vr = vbase + (size_t)(k0 + kloc) * KVD + dsg;
#pragma unroll
            for (int v = 0; v < 4; v++) {
                float4 kk = *(const float4*)(kr + v * 4);
                Ks[(dsg + v*4 + 0) * AK + kloc] = kk.x;
                Ks[(dsg + v*4 + 1) * AK + kloc] = kk.y;
                Ks[(dsg + v*4 + 2) * AK + kloc] = kk.z;
                Ks[(dsg + v*4 + 3) * AK + kloc] = kk.w;
                *(float4*)&Vs[kloc * AK + dsg + v*4] = *(const float4*)(vr + v * 4);
            }
        }
        __syncthreads();

        float s[8][4];
#pragma unroll
        for (int i = 0; i < 8; i++)
#pragma unroll
            for (int j = 0; j < 4; j++) s[i][j] = 0.f;

#pragma unroll 8
        for (int d = 0; d < 64; d++) {
            float4 kf = *(const float4*)&Ks[d * AK + tx * 4];
            float4 qa = *(const float4*)&Qs[d * AQ + ty * 8];
            float4 qb = *(const float4*)&Qs[d * AQ + ty * 8 + 4];
            float qf[8] = {qa.x, qa.y, qa.z, qa.w, qb.x, qb.y, qb.z, qb.w};
#pragma unroll
            for (int i = 0; i < 8; i++) {
                s[i][0] += qf[i] * kf.x;
                s[i][1] += qf[i] * kf.y;
                s[i][2] += qf[i] * kf.z;
                s[i][3] += qf[i] * kf.w;
            }
        }

#pragma unroll
        for (int i = 0; i < 8; i++) {
            int qg = q0 + ty * 8 + i;
#pragma unroll
            for (int j = 0; j < 4; j++) {
                int kj = k0 + tx * 4 + j;
                bool ok = (kj <= qg) && (qg - kj <= wl);
                if (!ok) s[i][j] = -INFINITY;
            }
            float mc = fmaxf(fmaxf(s[i][0], s[i][1]), fmaxf(s[i][2], s[i][3]));
            mc = fmaxf(mc, __shfl_xor_sync(gmask, mc, 1));
            mc = fmaxf(mc, __shfl_xor_sync(gmask, mc, 2));
            mc = fmaxf(mc, __shfl_xor_sync(gmask, mc, 4));
            mc = fmaxf(mc, __shfl_xor_sync(gmask, mc, 8));
            if (mc == -INFINITY) {
                s[i][0] = s[i][1] = s[i][2] = s[i][3] = 0.f;
            } else {
                float mnew = fmaxf(m[i], mc);
                float corr = exp2f(m[i] - mnew);
                l[i] *= corr;
                O[i][0] *= corr; O[i][1] *= corr; O[i][2] *= corr; O[i][3] *= corr;
                float sum = 0.f;
#pragma unroll
                for (int j = 0; j < 4; j++) {
                    s[i][j] = exp2f(s[i][j] - mnew);
                    sum += s[i][j];
                }
                sum += __shfl_xor_sync(gmask, sum, 1);
                sum += __shfl_xor_sync(gmask, sum, 2);
                sum += __shfl_xor_sync(gmask, sum, 4);
                sum += __shfl_xor_sync(gmask, sum, 8);
                l[i] += sum;
                m[i] = mnew;
            }
        }

        __syncthreads();
#pragma unroll
        for (int j = 0; j < 4; j++) {
            float* pr = &Ps[(tx * 4 + j) * AQ + ty * 8];
            *(float4*)(pr)     = make_float4(s[0][j], s[1][j], s[2][j], s[3][j]);
            *(float4*)(pr + 4) = make_float4(s[4][j], s[5][j], s[6][j], s[7][j]);
        }
        __syncthreads();

#pragma unroll 8
        for (int k = 0; k < 64; k++) {
            float4 vf = *(const float4*)&Vs[k * AK + tx * 4];
            float4 pa = *(const float4*)&Ps[k * AQ + ty * 8];
            float4 pb = *(const float4*)&Ps[k * AQ + ty * 8 + 4];
            float pf[8] = {pa.x, pa.y, pa.z, pa.w, pb.x, pb.y, pb.z, pb.w};
#pragma unroll
            for (int i = 0; i < 8; i++) {
                O[i][0] += pf[i] * vf.x;
                O[i][1] += pf[i] * vf.y;
                O[i][2] += pf[i] * vf.z;
                O[i][3] += pf[i] * vf.w;
            }
        }
    }

#pragma unroll
    for (int i = 0; i < 8; i++) {
        float inv = 1.0f / l[i];
        float* op = g_att + (size_t)(b * TT + q0 + ty * 8 + i) * CC + h * DD + tx * 4;
        *(float4*)op = make_float4(O[i][0]*inv, O[i][1]*inv, O[i][2]*inv, O[i][3]*inv);
    }
}

// ---------------- launch -----------------------------------------------------
extern "C" void kernel_launch(void* const* d_in, const int* in_sizes, int n_in,
                              void* d_out, int out_size) {
    const float* x     = (const float*)d_in[0];
    const float* wq    = (const float*)d_in[1];
    const float* wk    = (const float*)d_in[2];
    const float* wv    = (const float*)d_in[3];
    const float* wproj = (const float*)d_in[4];
    const float* qgain = (const float*)d_in[5];
    const int*   wl    = (const int*)d_in[6];
    float* out = (float*)d_out;

    cudaFuncSetAttribute(attn_kernel,
                         cudaFuncAttributeMaxDynamicSharedMemorySize,
                         ATTN_SMEM_BYTES);
    cudaFuncSetAttribute(qkv_gemm_kernel,
                         cudaFuncAttributeMaxDynamicSharedMemorySize,
                         GEMM_SMEM_BYTES);
    cudaFuncSetAttribute(proj_gemm_kernel,
                         cudaFuncAttributeMaxDynamicSharedMemorySize,
                         GEMM_SMEM_BYTES);

    rope_table_kernel<<<(TT * 8 + 255) / 256, 256>>>();

    dim3 g1(MM / 128, (CC + 2 * KVD) / 128);   // 32 x 12
    qkv_gemm_kernel<<<g1, 256, GEMM_SMEM_BYTES>>>(x, wq, wk, wv);

    int ntask = MM * (HH + HKVV);
    norm_rope_kernel<<<(ntask * 32 + 255) / 256, 256>>>();

    dim3 g2(HH * BB, TT / AQ);                 // 32 x 16
    attn_kernel<<<g2, 256, ATTN_SMEM_BYTES>>>(qgain, wl);

    dim3 g3(MM / 128, CC / 128);               // 32 x 8
    proj_gemm_kernel<<<g3, 256, GEMM_SMEM_BYTES>>>(out, wproj);
}

// round 10
// speedup vs baseline: 3.2654x; 1.7153x over previous
#include <cuda_runtime.h>
#include <cuda_bf16.h>
#include <math.h>
#include <cstdint>

// Problem constants (fixed by setup_inputs)
#define BB   2
#define TT   2048
#define CC   1024
#define HH   16
#define HKVV 4
#define DD   64
#define MM   (BB*TT)          // 4096 rows
#define KVD  (HKVV*DD)        // 256

// GEMM (mma.sync) tiling
#define KC   32               // fp32 K elements per chunk
#define NCH  (CC / KC)        // 32 chunks
#define SP   40               // smem row stride in bf16 elems (conflict-free)
#define BUFE (4 * 128 * SP)   // elems per buffer (4 arrays)
#define AHO  0
#define ALO  (128 * SP)
#define BHO  (2 * 128 * SP)
#define BLO  (3 * 128 * SP)
#define GEMM_SMEM_BYTES (2 * BUFE * 2)   // 81920 bytes

// ---------------- scratch (static device globals; no allocs allowed) --------
__device__ float g_q[MM * CC];      // 16 MB
__device__ float g_k[MM * KVD];     // 4 MB
__device__ float g_v[MM * KVD];     // 4 MB
__device__ float g_att[MM * CC];    // 16 MB
__device__ float g_cos[TT][8];
__device__ float g_sin[TT][8];

// ---------------- warp-level bf16 MMA (baseline PTX, valid on compute_100) --
__device__ __forceinline__ void mma_bf16(
    float* c, uint32_t a0, uint32_t a1, uint32_t a2, uint32_t a3,
    uint32_t b0, uint32_t b1)
{
    asm volatile(
        "mma.sync.aligned.m16n8k16.row.col.f32.bf16.bf16.f32 "
        "{%0,%1,%2,%3}, {%4,%5,%6,%7}, {%8,%9}, {%0,%1,%2,%3};"
        : "+f"(c[0]), "+f"(c[1]), "+f"(c[2]), "+f"(c[3])
        : "r"(a0), "r"(a1), "r"(a2), "r"(a3), "r"(b0), "r"(b1));
}

__device__ __forceinline__ uint32_t lds_b32(const __nv_bfloat16* p) {
    return *(const uint32_t*)p;
}

__device__ __forceinline__ float fast_exp2(float x) {
    float y;
    asm("ex2.approx.f32 %0, %1;" : "=f"(y) : "f"(x));
    return y;
}

__device__ __forceinline__ uint32_t smem_u32(const void* p) {
    uint32_t a;
    asm("{ .reg .u64 t; cvta.to.shared.u64 t, %1; cvt.u32.u64 %0, t; }"
        : "=r"(a) : "l"(p));
    return a;
}

__device__ __forceinline__ void ldsm_x2_trans(uint32_t addr, uint32_t& r0, uint32_t& r1) {
    asm volatile("ldmatrix.sync.aligned.m8n8.x2.trans.shared.b16 {%0,%1}, [%2];"
                 : "=r"(r0), "=r"(r1) : "r"(addr));
}

// split two fp32 into packed bf16x2 hi + lo(residual)
__device__ __forceinline__ void split2(float x, float y, uint32_t& hi, uint32_t& lo) {
    __nv_bfloat16 hx = __float2bfloat16_rn(x), hy = __float2bfloat16_rn(y);
    __nv_bfloat162 h2 = __halves2bfloat162(hx, hy);
    hi = *(uint32_t*)&h2;
    __nv_bfloat162 l2 = __floats2bfloat162_rn(x - __bfloat162float(hx),
                                              y - __bfloat162float(hy));
    lo = *(uint32_t*)&l2;
}

// ---------------- GEMM: convert 16 fp32 (4 float4) -> hi/lo bf16 rows -------
__device__ __forceinline__ void cvt_store16(
    __nv_bfloat16* hi, __nv_bfloat16* lo, uint32_t base, const float4* p)
{
#pragma unroll
    for (int j = 0; j < 4; j++) {
        float4 v = p[j];
        __nv_bfloat16 hx = __float2bfloat16_rn(v.x), hy = __float2bfloat16_rn(v.y);
        __nv_bfloat16 hz = __float2bfloat16_rn(v.z), hw = __float2bfloat16_rn(v.w);
        *(__nv_bfloat162*)(hi + base + j*4)     = __halves2bfloat162(hx, hy);
        *(__nv_bfloat162*)(hi + base + j*4 + 2) = __halves2bfloat162(hz, hw);
        *(__nv_bfloat162*)(lo + base + j*4) =
            __floats2bfloat162_rn(v.x - __bfloat162float(hx),
                                  v.y - __bfloat162float(hy));
        *(__nv_bfloat162*)(lo + base + j*4 + 2) =
            __floats2bfloat162_rn(v.z - __bfloat162float(hz),
                                  v.w - __bfloat162float(hw));
    }
}

__device__ __forceinline__ void gemm_compute_k16(
    const __nv_bfloat16* ah, const __nv_bfloat16* al,
    const __nv_bfloat16* bh, const __nv_bfloat16* bl,
    int mbase, int nbase, int g, int tg, int kk, float* acc)
{
    uint32_t bfh[8], bfl[8];
#pragma unroll
    for (int j = 0; j < 4; j++) {
        int r = (nbase + j*8 + g) * SP + kk + tg*2;
        bfh[2*j]   = lds_b32(bh + r);
        bfh[2*j+1] = lds_b32(bh + r + 8);
        bfl[2*j]   = lds_b32(bl + r);
        bfl[2*j+1] = lds_b32(bl + r + 8);
    }
#pragma unroll
    for (int i = 0; i < 4; i++) {
        int r0 = (mbase + i*16 + g) * SP + kk + tg*2;
        int r1 = r0 + 8 * SP;
        uint32_t a0 = lds_b32(ah + r0),     a1 = lds_b32(ah + r1);
        uint32_t a2 = lds_b32(ah + r0 + 8), a3 = lds_b32(ah + r1 + 8);
        uint32_t l0 = lds_b32(al + r0),     l1 = lds_b32(al + r1);
        uint32_t l2 = lds_b32(al + r0 + 8), l3 = lds_b32(al + r1 + 8);
#pragma unroll
        for (int j = 0; j < 4; j++) {
            float* c = acc + (i*4 + j) * 4;
            mma_bf16(c, a0, a1, a2, a3, bfh[2*j], bfh[2*j+1]);
            mma_bf16(c, a0, a1, a2, a3, bfl[2*j], bfl[2*j+1]);
            mma_bf16(c, l0, l1, l2, l3, bfh[2*j], bfh[2*j+1]);
        }
    }
}

__device__ __forceinline__ void mma_gemm_body(
    const float* __restrict__ A, const float* __restrict__ W,
    float* __restrict__ Y, int ldy, int m0, int n0w, int n0y)
{
    extern __shared__ __nv_bfloat16 gsm[];

    int tid = threadIdx.x, wid = tid >> 5, lane = tid & 31;
    int g = lane >> 2, tg = lane & 3;
    int mbase = (wid & 1) * 64;
    int nbase = (wid >> 1) * 32;

    int lrow  = tid >> 1;
    int lhalf = (tid & 1) * 16;
    const float* gA = A + (size_t)(m0  + lrow) * CC + lhalf;
    const float* gW = W + (size_t)(n0w + lrow) * CC + lhalf;
    uint32_t sbase = lrow * SP + lhalf;

    float acc[64];
#pragma unroll
    for (int i = 0; i < 64; i++) acc[i] = 0.f;

    float4 pa[4], pw[4];
#pragma unroll
    for (int j = 0; j < 4; j++) {
        pa[j] = *(const float4*)(gA + j*4);
        pw[j] = *(const float4*)(gW + j*4);
    }
    cvt_store16(gsm + AHO, gsm + ALO, sbase, pa);
    cvt_store16(gsm + BHO, gsm + BLO, sbase, pw);
    __syncthreads();

#pragma unroll 1
    for (int ch = 0; ch < NCH; ch++) {
        __nv_bfloat16* cur = gsm + (ch & 1) * BUFE;
        __nv_bfloat16* nxt = gsm + ((ch + 1) & 1) * BUFE;
        if (ch < NCH - 1) {
            int kc = (ch + 1) * KC;
#pragma unroll
            for (int j = 0; j < 4; j++) {
                pa[j] = *(const float4*)(gA + kc + j*4);
                pw[j] = *(const float4*)(gW + kc + j*4);
            }
        }
        gemm_compute_k16(cur + AHO, cur + ALO, cur + BHO, cur + BLO,
                         mbase, nbase, g, tg, 0, acc);
        gemm_compute_k16(cur + AHO, cur + ALO, cur + BHO, cur + BLO,
                         mbase, nbase, g, tg, 16, acc);
        if (ch < NCH - 1) {
            cvt_store16(nxt + AHO, nxt + ALO, sbase, pa);
            cvt_store16(nxt + BHO, nxt + BLO, sbase, pw);
        }
        __syncthreads();
    }

#pragma unroll
    for (int i = 0; i < 4; i++) {
#pragma unroll
        for (int j = 0; j < 4; j++) {
            float* c = acc + (i*4 + j) * 4;
            int mrow = m0  + mbase + i*16 + g;
            int ncol = n0y + nbase + j*8 + tg*2;
            *(float2*)&Y[(size_t)mrow * ldy + ncol]       = make_float2(c[0], c[1]);
            *(float2*)&Y[(size_t)(mrow + 8) * ldy + ncol] = make_float2(c[2], c[3]);
        }
    }
}

__global__ __launch_bounds__(256, 1) void qkv_gemm_kernel(
    const float* __restrict__ x, const float* __restrict__ wq,
    const float* __restrict__ wk, const float* __restrict__ wv)
{
    int n0 = blockIdx.y * 128;
    const float* W; float* Y; int n0w, ldy;
    if (n0 < CC)            { W = wq; Y = g_q; n0w = n0;            ldy = CC;  }
    else if (n0 < CC + KVD) { W = wk; Y = g_k; n0w = n0 - CC;       ldy = KVD; }
    else                    { W = wv; Y = g_v; n0w = n0 - CC - KVD; ldy = KVD; }
    mma_gemm_body(x, W, Y, ldy, blockIdx.x * 128, n0w, n0w);
}

__global__ __launch_bounds__(256, 1) void proj_gemm_kernel(
    float* __restrict__ out, const float* __restrict__ wproj)
{
    mma_gemm_body(g_att, wproj, out, CC, blockIdx.x * 128,
                  blockIdx.y * 128, blockIdx.y * 128);
}

// ---------------- RoPE table (double precision of fp32 angle) ---------------
__global__ void rope_table_kernel() {
    int idx = blockIdx.x * blockDim.x + threadIdx.x;   // 0 .. TT*8-1
    if (idx >= TT * 8) return;
    int t = idx >> 3;
    int i = idx & 7;
    double inv_d = exp2(-((double)(2 * i) / 64.0) * 13.28771237954945);  // log2(10000)
    float inv_f = (float)inv_d;
    float ang = (float)t * inv_f;              // fp32 product, like jnp.outer
    g_cos[t][i] = (float)cos((double)ang);
    g_sin[t][i] = (float)sin((double)ang);
}

// ---------------- RMS norm + partial RoPE (one warp per head vector) --------
__global__ void norm_rope_kernel() {
    int gtid = blockIdx.x * blockDim.x + threadIdx.x;
    int task = gtid >> 5;
    int lane = gtid & 31;
    const int NTASK = MM * (HH + HKVV);
    if (task >= NTASK) return;
    int row = task / (HH + HKVV);
    int hh  = task % (HH + HKVV);
    float* base = (hh < HH) ? (g_q + (size_t)row * CC + hh * DD)
                            : (g_k + (size_t)row * KVD + (hh - HH) * DD);
    float v0 = base[lane];
    float v1 = base[lane + 32];
    float ss = v0 * v0 + v1 * v1;
#pragma unroll
    for (int o = 16; o; o >>= 1) ss += __shfl_xor_sync(0xffffffffu, ss, o);
    float a = ss * (1.0f / 64.0f) + 1.1920929e-07f;
    float r = rsqrtf(a);
    r = r * (1.5f - 0.5f * a * r * r);
    v0 *= r; v1 *= r;
    int t = row % TT;
    float p = __shfl_xor_sync(0xffffffffu, v0, 8);
    if (lane < 16) {
        int i = lane & 7;
        float c = g_cos[t][i], s = g_sin[t][i];
        v0 = (lane < 8) ? (v0 * c + p * s) : (v0 * c - p * s);
    }
    base[lane] = v0;
    base[lane + 32] = v1;
}

// ---------------- flash attention on tensor cores (mma.sync, bf16-split) ----
// CTA: 128 queries (8 warps x 16q), 64-key tiles. Per warp: S[16x64] via
// m16n8k16 (8 n-frags x 4 k-steps x 3 split terms), register softmax
// (shfl over 4-thread row groups), P stays in registers as PV A-fragments.
// K smem: pair-interleaved {hi2,lo2} uint2 (one LDS.64 per split pair).
// V smem: row-major bf16 hi/lo, B-frags via ldmatrix.x2.trans.
__global__ __launch_bounds__(256) void attn_kernel(
    const float* __restrict__ qgain, const int* __restrict__ wl_ptr)
{
    __shared__ uint2    sK[64][36];      // [key][dim-pair] {hi2, lo2} (pad 36)
    __shared__ uint32_t sVh[64][36];     // [key][dim-pair] bf16x2 hi (stride 144B)
    __shared__ uint32_t sVl[64][36];     // lo

    int tid  = threadIdx.x;
    int w    = tid >> 5;
    int lane = tid & 31;
    int g    = lane >> 2, tg = lane & 3;
    int ln15 = lane & 15;

    int h  = blockIdx.x & 15;
    int b  = blockIdx.x >> 4;
    int q0 = (int)(gridDim.y - 1 - blockIdx.y) * 128;   // heavy CTAs first
    int kvh = h >> 2;

    int wl = *wl_ptr;
    if (wl < 0) wl = TT;

    float qscale = qgain[h] * 0.125f * 1.4426950408889634f;

    int qr0  = q0 + w * 16 + g;         // this thread's row (and qr0+8)
    int qr1  = qr0 + 8;
    int qrmin = q0 + w * 16;
    int qrmax = qrmin + 15;

    // ---- Q fragments (hi/lo), loaded once ----
    uint32_t aqh[4][4], aql[4][4];
    {
        const float* qb0 = g_q + (size_t)(b * TT + qr0) * CC + h * DD;
        const float* qb1 = qb0 + 8 * CC;
#pragma unroll
        for (int s = 0; s < 4; s++) {
            int c = 16 * s + 2 * tg;
            float2 x0 = *(const float2*)(qb0 + c);
            float2 x1 = *(const float2*)(qb1 + c);
            float2 x2 = *(const float2*)(qb0 + c + 8);
            float2 x3 = *(const float2*)(qb1 + c + 8);
            split2(x0.x * qscale, x0.y * qscale, aqh[s][0], aql[s][0]);
            split2(x1.x * qscale, x1.y * qscale, aqh[s][1], aql[s][1]);
            split2(x2.x * qscale, x2.y * qscale, aqh[s][2], aql[s][2]);
            split2(x3.x * qscale, x3.y * qscale, aqh[s][3], aql[s][3]);
        }
    }

    float O[8][4];
#pragma unroll
    for (int j = 0; j < 8; j++)
#pragma unroll
        for (int c = 0; c < 4; c++) O[j][c] = 0.f;
    float m0 = -INFINITY, m1 = -INFINITY, l0 = 0.f, l1 = 0.f;

    int lo_b = q0 - wl;
    int kt_lo = (lo_b > 0) ? (lo_b / 64) : 0;
    int kt_hi = (q0 + 127) / 64;

    const float* kbase = g_k + (size_t)b * TT * KVD + kvh * DD;
    const float* vbase = g_v + (size_t)b * TT * KVD + kvh * DD;

    // loader mapping: pair lp (dims 2lp,2lp+1), key group lk0..lk0+7
    int lp  = tid & 31;
    int lk0 = (tid >> 5) * 8;

    uint32_t vh_base = smem_u32(sVh);
    uint32_t vl_base = smem_u32(sVl);

    // prefetch first tile into regs
    float2 pk[8], pv[8];
    {
        int k0 = kt_lo * 64;
#pragma unroll
        for (int i = 0; i < 8; i++) {
            const float* kr = kbase + (size_t)(k0 + lk0 + i) * KVD + 2 * lp;
            const float* vr = vbase + (size_t)(k0 + lk0 + i) * KVD + 2 * lp;
            pk[i] = *(const float2*)kr;
            pv[i] = *(const float2*)vr;
        }
    }

#pragma unroll 1
    for (int kt = kt_lo; kt <= kt_hi; kt++) {
        int k0 = kt * 64;
        __syncthreads();    // previous tile compute done
        // store prefetched K/V (split on the fly)
#pragma unroll
        for (int i = 0; i < 8; i++) {
            int key = lk0 + i;
            uint32_t khi, klo, vhi, vlo;
            split2(pk[i].x, pk[i].y, khi, klo);
            split2(pv[i].x, pv[i].y, vhi, vlo);
            sK[key][lp]  = make_uint2(khi, klo);
            sVh[key][lp] = vhi;
            sVl[key][lp] = vlo;
        }
        __syncthreads();    // smem tile ready
        // prefetch next tile
        if (kt < kt_hi) {
            int kn = k0 + 64;
#pragma unroll
            for (int i = 0; i < 8; i++) {
                const float* kr = kbase + (size_t)(kn + lk0 + i) * KVD + 2 * lp;
                const float* vr = vbase + (size_t)(kn + lk0 + i) * KVD + 2 * lp;
                pk[i] = *(const float2*)kr;
                pv[i] = *(const float2*)vr;
            }
        }

        // warp-uniform liveness
        if (k0 > qrmax || k0 + 63 < qrmin - wl) continue;

        // ---- QK^T: S[16x64] ----
        float S[8][4];
#pragma unroll
        for (int j = 0; j < 8; j++)
#pragma unroll
            for (int c = 0; c < 4; c++) S[j][c] = 0.f;

#pragma unroll
        for (int s = 0; s < 4; s++) {
#pragma unroll
            for (int j = 0; j < 8; j++) {
                uint2 p0 = sK[8 * j + g][8 * s + tg];
                uint2 p1 = sK[8 * j + g][8 * s + 4 + tg];
                mma_bf16(S[j], aqh[s][0], aqh[s][1], aqh[s][2], aqh[s][3], p0.x, p1.x);
                mma_bf16(S[j], aqh[s][0], aqh[s][1], aqh[s][2], aqh[s][3], p0.y, p1.y);
                mma_bf16(S[j], aql[s][0], aql[s][1], aql[s][2], aql[s][3], p0.x, p1.x);
            }
        }

        // ---- mask + row max ----
        float mc0 = -INFINITY, mc1 = -INFINITY;
#pragma unroll
        for (int j = 0; j < 8; j++) {
            int kj = k0 + 8 * j + 2 * tg;
            if (!(kj     <= qr0 && qr0 - kj     <= wl)) S[j][0] = -INFINITY;
            if (!(kj + 1 <= qr0 && qr0 - kj - 1 <= wl)) S[j][1] = -INFINITY;
            if (!(kj     <= qr1 && qr1 - kj     <= wl)) S[j][2] = -INFINITY;
            if (!(kj + 1 <= qr1 && qr1 - kj - 1 <= wl)) S[j][3] = -INFINITY;
            mc0 = fmaxf(mc0, fmaxf(S[j][0], S[j][1]));
            mc1 = fmaxf(mc1, fmaxf(S[j][2], S[j][3]));
        }
        mc0 = fmaxf(mc0, __shfl_xor_sync(0xffffffffu, mc0, 1));
        mc0 = fmaxf(mc0, __shfl_xor_sync(0xffffffffu, mc0, 2));
        mc1 = fmaxf(mc1, __shfl_xor_sync(0xffffffffu, mc1, 1));
        mc1 = fmaxf(mc1, __shfl_xor_sync(0xffffffffu, mc1, 2));

        // ---- online softmax into P (reuse S storage) ----
        if (mc0 > -INFINITY) {
            float mn = fmaxf(m0, mc0);
            float corr = fast_exp2(m0 - mn);    // m0=-inf -> 0
            m0 = mn; l0 *= corr;
            float sum = 0.f;
#pragma unroll
            for (int j = 0; j < 8; j++) {
                O[j][0] *= corr; O[j][1] *= corr;
                S[j][0] = fast_exp2(S[j][0] - m0);
                S[j][1] = fast_exp2(S[j][1] - m0);
                sum += S[j][0] + S[j][1];
            }
            l0 += sum;
        } else {
#pragma unroll
            for (int j = 0; j < 8; j++) { S[j][0] = 0.f; S[j][1] = 0.f; }
        }
        if (mc1 > -INFINITY) {
            float mn = fmaxf(m1, mc1);
            float corr = fast_exp2(m1 - mn);
            m1 = mn; l1 *= corr;
            float sum = 0.f;
#pragma unroll
            for (int j = 0; j < 8; j++) {
                O[j][2] *= corr; O[j][3] *= corr;
                S[j][2] = fast_exp2(S[j][2] - m1);
                S[j][3] = fast_exp2(S[j][3] - m1);
                sum += S[j][2] + S[j][3];
            }
            l1 += sum;
        } else {
#pragma unroll
            for (int j = 0; j < 8; j++) { S[j][2] = 0.f; S[j][3] = 0.f; }
        }

        // ---- pack P into PV A-fragments (hi/lo) ----
        uint32_t pah[4][4], pal[4][4];
#pragma unroll
        for (int s = 0; s < 4; s++) {
            split2(S[2*s][0],   S[2*s][1],   pah[s][0], pal[s][0]);
            split2(S[2*s][2],   S[2*s][3],   pah[s][1], pal[s][1]);
            split2(S[2*s+1][0], S[2*s+1][1], pah[s][2], pal[s][2]);
            split2(S[2*s+1][2], S[2*s+1][3], pah[s][3], pal[s][3]);
        }

        // ---- P @ V ----
#pragma unroll
        for (int s = 0; s < 4; s++) {
            uint32_t rowh = vh_base + (16 * s + ln15) * 144;
            uint32_t rowl = vl_base + (16 * s + ln15) * 144;
#pragma unroll
            for (int j = 0; j < 8; j++) {
                uint32_t bh0, bh1, bl0, bl1;
                ldsm_x2_trans(rowh + 16 * j, bh0, bh1);
                ldsm_x2_trans(rowl + 16 * j, bl0, bl1);
                mma_bf16(O[j], pah[s][0], pah[s][1], pah[s][2], pah[s][3], bh0, bh1);
                mma_bf16(O[j], pah[s][0], pah[s][1], pah[s][2], pah[s][3], bl0, bl1);
                mma_bf16(O[j], pal[s][0], pal[s][1], pal[s][2], pal[s][3], bh0, bh1);
            }
        }
    }

    // ---- epilogue ----
    l0 += __shfl_xor_sync(0xffffffffu, l0, 1);
    l0 += __shfl_xor_sync(0xffffffffu, l0, 2);
    l1 += __shfl_xor_sync(0xffffffffu, l1, 1);
    l1 += __shfl_xor_sync(0xffffffffu, l1, 2);
    float inv0 = 1.0f / l0;
    float inv1 = 1.0f / l1;
    float* ob0 = g_att + (size_t)(b * TT + qr0) * CC + h * DD;
    float* ob1 = ob0 + 8 * CC;
#pragma unroll
    for (int j = 0; j < 8; j++) {
        int col = 8 * j + 2 * tg;
        *(float2*)(ob0 + col) = make_float2(O[j][0] * inv0, O[j][1] * inv0);
        *(float2*)(ob1 + col) = make_float2(O[j][2] * inv1, O[j][3] * inv1);
    }
}

// ---------------- launch -----------------------------------------------------
extern "C" void kernel_launch(void* const* d_in, const int* in_sizes, int n_in,
                              void* d_out, int out_size) {
    const float* x     = (const float*)d_in[0];
    const float* wq    = (const float*)d_in[1];
    const float* wk    = (const float*)d_in[2];
    const float* wv    = (const float*)d_in[3];
    const float* wproj = (const float*)d_in[4];
    const float* qgain = (const float*)d_in[5];
    const int*   wl    = (const int*)d_in[6];
    float* out = (float*)d_out;

    cudaFuncSetAttribute(qkv_gemm_kernel,
                         cudaFuncAttributeMaxDynamicSharedMemorySize,
                         GEMM_SMEM_BYTES);
    cudaFuncSetAttribute(proj_gemm_kernel,
                         cudaFuncAttributeMaxDynamicSharedMemorySize,
                         GEMM_SMEM_BYTES);

    rope_table_kernel<<<(TT * 8 + 255) / 256, 256>>>();

    dim3 g1(MM / 128, (CC + 2 * KVD) / 128);   // 32 x 12
    qkv_gemm_kernel<<<g1, 256, GEMM_SMEM_BYTES>>>(x, wq, wk, wv);

    int ntask = MM * (HH + HKVV);
    norm_rope_kernel<<<(ntask * 32 + 255) / 256, 256>>>();

    dim3 g2(HH * BB, TT / 128);                // 32 x 16
    attn_kernel<<<g2, 256>>>(qgain, wl);

    dim3 g3(MM / 128, CC / 128);               // 32 x 8
    proj_gemm_kernel<<<g3, 256, GEMM_SMEM_BYTES>>>(out, wproj);
}

// round 11
// speedup vs baseline: 3.8948x; 1.1927x over previous
#include <cuda_runtime.h>
#include <cuda_bf16.h>
#include <math.h>
#include <cstdint>

// Problem constants (fixed by setup_inputs)
#define BB   2
#define TT   2048
#define CC   1024
#define HH   16
#define HKVV 4
#define DD   64
#define MM   (BB*TT)          // 4096 rows
#define KVD  (HKVV*DD)        // 256
#define NW   (CC + 2*KVD)     // 1536 fused qkv output rows

typedef __nv_bfloat16  bf16;
typedef __nv_bfloat162 bf162;

// ---------------- scratch (static device globals; no allocs allowed) --------
__device__ float g_q[MM * CC];      // qkv fp32 out (pre-norm)
__device__ float g_k[MM * KVD];
__device__ __align__(128) bf16 g_xh[MM * CC],  g_xl[MM * CC];
__device__ __align__(128) bf16 g_wfh[NW * CC], g_wfl[NW * CC];   // wq|wk|wv fused
__device__ __align__(128) bf16 g_wph[CC * CC], g_wpl[CC * CC];
__device__ __align__(128) bf16 g_qh[MM * CC],  g_ql[MM * CC];    // post norm/rope/scale
__device__ __align__(128) bf16 g_kh[MM * KVD], g_kl[MM * KVD];
__device__ __align__(128) bf16 g_vh[MM * KVD], g_vl[MM * KVD];
__device__ __align__(128) bf16 g_ah[MM * CC],  g_al[MM * CC];    // attention out
__device__ float g_cos[TT][8];
__device__ float g_sin[TT][8];

// ---------------- PTX helpers ------------------------------------------------
__device__ __forceinline__ void mma_bf16(
    float* c, uint32_t a0, uint32_t a1, uint32_t a2, uint32_t a3,
    uint32_t b0, uint32_t b1)
{
    asm volatile(
        "mma.sync.aligned.m16n8k16.row.col.f32.bf16.bf16.f32 "
        "{%0,%1,%2,%3}, {%4,%5,%6,%7}, {%8,%9}, {%0,%1,%2,%3};"
        : "+f"(c[0]), "+f"(c[1]), "+f"(c[2]), "+f"(c[3])
        : "r"(a0), "r"(a1), "r"(a2), "r"(a3), "r"(b0), "r"(b1));
}
__device__ __forceinline__ uint32_t lds_b32(const bf16* p) {
    return *(const uint32_t*)p;
}
__device__ __forceinline__ float fast_exp2(float x) {
    float y; asm("ex2.approx.f32 %0, %1;" : "=f"(y) : "f"(x)); return y;
}
__device__ __forceinline__ uint32_t smem_u32(const void* p) {
    uint32_t a;
    asm("{ .reg .u64 t; cvta.to.shared.u64 t, %1; cvt.u32.u64 %0, t; }"
        : "=r"(a) : "l"(p));
    return a;
}
__device__ __forceinline__ void ldsm_x2_trans(uint32_t addr, uint32_t& r0, uint32_t& r1) {
    asm volatile("ldmatrix.sync.aligned.m8n8.x2.trans.shared.b16 {%0,%1}, [%2];"
                 : "=r"(r0), "=r"(r1) : "r"(addr));
}
__device__ __forceinline__ void cp16(uint32_t dst, const void* src) {
    asm volatile("cp.async.cg.shared.global [%0], [%1], 16;" :: "r"(dst), "l"(src));
}
#define CP_COMMIT() asm volatile("cp.async.commit_group;" ::: "memory")
#define CP_WAIT1()  asm volatile("cp.async.wait_group 1;"  ::: "memory")
#define CP_WAIT0()  asm volatile("cp.async.wait_group 0;"  ::: "memory")

// split two fp32 into packed bf16x2 hi + lo(residual)
__device__ __forceinline__ void split2(float x, float y, uint32_t& hi, uint32_t& lo) {
    bf16 hx = __float2bfloat16_rn(x), hy = __float2bfloat16_rn(y);
    bf162 h2 = __halves2bfloat162(hx, hy);
    hi = *(uint32_t*)&h2;
    bf162 l2 = __floats2bfloat162_rn(x - __bfloat162float(hx),
                                     y - __bfloat162float(hy));
    lo = *(uint32_t*)&l2;
}

// ---------------- pre-convert: fp32 -> (hi, lo) bf16 ------------------------
__global__ void cvt_all_kernel(
    const float* __restrict__ x,  const float* __restrict__ wq,
    const float* __restrict__ wk, const float* __restrict__ wv,
    const float* __restrict__ wp)
{
    const int N0 = MM * CC / 4;
    const int N1 = N0 + CC * CC / 4;
    const int N2 = N1 + KVD * CC / 4;
    const int N3 = N2 + KVD * CC / 4;
    const int N4 = N3 + CC * CC / 4;
    int i = blockIdx.x * blockDim.x + threadIdx.x;
    if (i >= N4) return;
    const float* src; bf16* hi; bf16* lo; int q;
    if (i < N0)      { src = x;  hi = g_xh;  lo = g_xl;  q = i; }
    else if (i < N1) { src = wq; hi = g_wfh; lo = g_wfl; q = i - N0; }
    else if (i < N2) { src = wk; hi = g_wfh + (size_t)CC * CC;
                       lo = g_wfl + (size_t)CC * CC;               q = i - N1; }
    else if (i < N3) { src = wv; hi = g_wfh + (size_t)(CC + KVD) * CC;
                       lo = g_wfl + (size_t)(CC + KVD) * CC;       q = i - N2; }
    else             { src = wp; hi = g_wph; lo = g_wpl; q = i - N3; }
    float4 v = ((const float4*)src)[q];
    bf16 hx = __float2bfloat16_rn(v.x), hy = __float2bfloat16_rn(v.y);
    bf16 hz = __float2bfloat16_rn(v.z), hw = __float2bfloat16_rn(v.w);
    ((bf162*)hi)[2*q]   = __halves2bfloat162(hx, hy);
    ((bf162*)hi)[2*q+1] = __halves2bfloat162(hz, hw);
    ((bf162*)lo)[2*q]   = __floats2bfloat162_rn(v.x - __bfloat162float(hx),
                                                v.y - __bfloat162float(hy));
    ((bf162*)lo)[2*q+1] = __floats2bfloat162_rn(v.z - __bfloat162float(hz),
                                                v.w - __bfloat162float(hw));
}

// ---------------- GEMM: pure-bf16 cp.async pipeline + mma.sync ---------------
#define SP     40                 // smem row stride (bf16 elems), conflict-free
#define GARR   (128 * SP)         // 5120 elems per array
#define GSTAGE (4 * GARR)         // Ah,Al,Bh,Bl
#define GEMM_SMEM_BYTES (2 * GSTAGE * 2)   // 81920 B (2 stages)

__device__ __forceinline__ void gemm_issue(
    const bf16* Ah, const bf16* Al, const bf16* Bh, const bf16* Bl,
    uint32_t sb, int st, int ch)
{
    int tid = threadIdx.x;
    int r   = tid >> 1;
    int s0  = (tid & 1) * 2;
    size_t go = (size_t)r * CC + ch * 32 + s0 * 8;
    uint32_t d = sb + (uint32_t)(st * GSTAGE + r * SP + s0 * 8) * 2;
    const uint32_t AB = GARR * 2;
    cp16(d,               Ah + go);
    cp16(d + 16,          Ah + go + 8);
    cp16(d + AB,          Al + go);
    cp16(d + AB + 16,     Al + go + 8);
    cp16(d + 2*AB,        Bh + go);
    cp16(d + 2*AB + 16,   Bh + go + 8);
    cp16(d + 3*AB,        Bl + go);
    cp16(d + 3*AB + 16,   Bl + go + 8);
}

__device__ __forceinline__ void gemm_compute_k16(
    const bf16* ah, const bf16* al, const bf16* bh, const bf16* bl,
    int mbase, int nbase, int g, int tg, int kk, float* acc)
{
    uint32_t bfh[8], bfl[8];
#pragma unroll
    for (int j = 0; j < 4; j++) {
        int r = (nbase + j*8 + g) * SP + kk + tg*2;
        bfh[2*j]   = lds_b32(bh + r);
        bfh[2*j+1] = lds_b32(bh + r + 8);
        bfl[2*j]   = lds_b32(bl + r);
        bfl[2*j+1] = lds_b32(bl + r + 8);
    }
#pragma unroll
    for (int i = 0; i < 4; i++) {
        int r0 = (mbase + i*16 + g) * SP + kk + tg*2;
        int r1 = r0 + 8 * SP;
        uint32_t a0 = lds_b32(ah + r0),     a1 = lds_b32(ah + r1);
        uint32_t a2 = lds_b32(ah + r0 + 8), a3 = lds_b32(ah + r1 + 8);
        uint32_t l0 = lds_b32(al + r0),     l1 = lds_b32(al + r1);
        uint32_t l2 = lds_b32(al + r0 + 8), l3 = lds_b32(al + r1 + 8);
#pragma unroll
        for (int j = 0; j < 4; j++) {
            float* c = acc + (i*4 + j) * 4;
            mma_bf16(c, a0, a1, a2, a3, bfh[2*j], bfh[2*j+1]);
            mma_bf16(c, a0, a1, a2, a3, bfl[2*j], bfl[2*j+1]);
            mma_bf16(c, l0, l1, l2, l3, bfh[2*j], bfh[2*j+1]);
        }
    }
}

// Y tile = A[128,1024] @ B[128,1024]^T; operands pre-offset to tile origin.
// vout: write bf16 hi/lo to g_vh/g_vl instead of fp32 Y.
__device__ __forceinline__ void bf16_gemm_body(
    const bf16* Ah, const bf16* Al, const bf16* Bh, const bf16* Bl,
    float* Y, int ldy, int m0, int n0y, int vout)
{
    extern __shared__ bf16 gsm[];
    uint32_t sb = smem_u32(gsm);
    int tid = threadIdx.x, wid = tid >> 5, lane = tid & 31;
    int g = lane >> 2, tg = lane & 3;
    int mbase = (wid & 1) * 64;
    int nbase = (wid >> 1) * 32;

    float acc[64];
#pragma unroll
    for (int i = 0; i < 64; i++) acc[i] = 0.f;

    gemm_issue(Ah, Al, Bh, Bl, sb, 0, 0);
    CP_COMMIT();

#pragma unroll 1
    for (int ch = 0; ch < 32; ch++) {
        int st = ch & 1;
        if (ch < 31) {
            gemm_issue(Ah, Al, Bh, Bl, sb, st ^ 1, ch + 1);
            CP_COMMIT();
            CP_WAIT1();
        } else {
            CP_WAIT0();
        }
        __syncthreads();
        const bf16* s = gsm + st * GSTAGE;
        gemm_compute_k16(s, s + GARR, s + 2*GARR, s + 3*GARR,
                         mbase, nbase, g, tg, 0, acc);
        gemm_compute_k16(s, s + GARR, s + 2*GARR, s + 3*GARR,
                         mbase, nbase, g, tg, 16, acc);
        __syncthreads();
    }

#pragma unroll
    for (int i = 0; i < 4; i++) {
#pragma unroll
        for (int j = 0; j < 4; j++) {
            float* c = acc + (i*4 + j) * 4;
            int mrow = m0 + mbase + i*16 + g;
            int ncol = n0y + nbase + j*8 + tg*2;
            if (!vout) {
                *(float2*)&Y[(size_t)mrow * ldy + ncol]       = make_float2(c[0], c[1]);
                *(float2*)&Y[(size_t)(mrow + 8) * ldy + ncol] = make_float2(c[2], c[3]);
            } else {
                uint32_t ph, pl;
                split2(c[0], c[1], ph, pl);
                *(uint32_t*)&g_vh[(size_t)mrow * KVD + ncol] = ph;
                *(uint32_t*)&g_vl[(size_t)mrow * KVD + ncol] = pl;
                split2(c[2], c[3], ph, pl);
                *(uint32_t*)&g_vh[(size_t)(mrow + 8) * KVD + ncol] = ph;
                *(uint32_t*)&g_vl[(size_t)(mrow + 8) * KVD + ncol] = pl;
            }
        }
    }
}

__global__ __launch_bounds__(256, 2) void qkv_gemm_kernel() {
    int m0 = blockIdx.x * 128;
    int n0 = blockIdx.y * 128;
    const bf16* Ah = g_xh + (size_t)m0 * CC;
    const bf16* Al = g_xl + (size_t)m0 * CC;
    const bf16* Bh = g_wfh + (size_t)n0 * CC;
    const bf16* Bl = g_wfl + (size_t)n0 * CC;
    if (n0 < CC)
        bf16_gemm_body(Ah, Al, Bh, Bl, g_q, CC, m0, n0, 0);
    else if (n0 < CC + KVD)
        bf16_gemm_body(Ah, Al, Bh, Bl, g_k, KVD, m0, n0 - CC, 0);
    else
        bf16_gemm_body(Ah, Al, Bh, Bl, nullptr, KVD, m0, n0 - CC - KVD, 1);
}

__global__ __launch_bounds__(256, 2) void proj_gemm_kernel(float* __restrict__ out) {
    int m0 = blockIdx.x * 128;
    int n0 = blockIdx.y * 128;
    bf16_gemm_body(g_ah + (size_t)m0 * CC, g_al + (size_t)m0 * CC,
                   g_wph + (size_t)n0 * CC, g_wpl + (size_t)n0 * CC,
                   out, CC, m0, n0, 0);
}

// ---------------- RoPE table (double precision of fp32 angle) ---------------
__global__ void rope_table_kernel() {
    int idx = blockIdx.x * blockDim.x + threadIdx.x;
    if (idx >= TT * 8) return;
    int t = idx >> 3;
    int i = idx & 7;
    double inv_d = exp2(-((double)(2 * i) / 64.0) * 13.28771237954945);
    float inv_f = (float)inv_d;
    float ang = (float)t * inv_f;
    g_cos[t][i] = (float)cos((double)ang);
    g_sin[t][i] = (float)sin((double)ang);
}

// ---- RMS norm + partial RoPE (+qscale for q) -> bf16 hi/lo -----------------
__global__ void norm_rope_kernel(const float* __restrict__ qgain) {
    int gtid = blockIdx.x * blockDim.x + threadIdx.x;
    int task = gtid >> 5;
    int lane = gtid & 31;
    const int NTASK = MM * (HH + HKVV);
    if (task >= NTASK) return;
    int row = task / (HH + HKVV);
    int hh  = task % (HH + HKVV);
    const float* base = (hh < HH) ? (g_q + (size_t)row * CC + hh * DD)
                                  : (g_k + (size_t)row * KVD + (hh - HH) * DD);
    float v0 = base[lane];
    float v1 = base[lane + 32];
    float ss = v0 * v0 + v1 * v1;
#pragma unroll
    for (int o = 16; o; o >>= 1) ss += __shfl_xor_sync(0xffffffffu, ss, o);
    float a = ss * (1.0f / 64.0f) + 1.1920929e-07f;
    float r = rsqrtf(a);
    r = r * (1.5f - 0.5f * a * r * r);
    v0 *= r; v1 *= r;
    int t = row % TT;
    float p = __shfl_xor_sync(0xffffffffu, v0, 8);
    if (lane < 16) {
        int i = lane & 7;
        float c = g_cos[t][i], s = g_sin[t][i];
        v0 = (lane < 8) ? (v0 * c + p * s) : (v0 * c - p * s);
    }
    if (hh < HH) {
        float qsc = qgain[hh] * 0.125f * 1.4426950408889634f;
        v0 *= qsc; v1 *= qsc;
        size_t o = (size_t)row * CC + hh * DD + lane;
        bf16 h0 = __float2bfloat16_rn(v0);
        bf16 h1 = __float2bfloat16_rn(v1);
        g_qh[o]      = h0; g_ql[o]      = __float2bfloat16_rn(v0 - __bfloat162float(h0));
        g_qh[o + 32] = h1; g_ql[o + 32] = __float2bfloat16_rn(v1 - __bfloat162float(h1));
    } else {
        size_t o = (size_t)row * KVD + (hh - HH) * DD + lane;
        bf16 h0 = __float2bfloat16_rn(v0);
        bf16 h1 = __float2bfloat16_rn(v1);
        g_kh[o]      = h0; g_kl[o]      = __float2bfloat16_rn(v0 - __bfloat162float(h0));
        g_kh[o + 32] = h1; g_kl[o + 32] = __float2bfloat16_rn(v1 - __bfloat162float(h1));
    }
}

// ---------------- flash attention (mma.sync, pre-split operands) -------------
#define ASP  72                    // smem row stride (bf16 elems)
#define AARR (64 * ASP)            // 4608 elems
#define ASTG (4 * AARR)            // Kh,Kl,Vh,Vl
#define ATTN_SMEM_BYTES (2 * ASTG * 2)   // 73728 B

__device__ __forceinline__ void attn_issue(
    const bf16* kh, const bf16* kl, const bf16* vh, const bf16* vl,
    uint32_t sb, int st, int k0)
{
    int tid = threadIdx.x;
    int r   = tid >> 2;                  // key row 0..63
    int s0  = (tid & 3) * 2;             // segs s0, s0+1 (of 8)
    size_t go = (size_t)(k0 + r) * KVD + s0 * 8;
    uint32_t d = sb + (uint32_t)(st * ASTG + r * ASP + s0 * 8) * 2;
    const uint32_t AB = AARR * 2;
    cp16(d,               kh + go);
    cp16(d + 16,          kh + go + 8);
    cp16(d + AB,          kl + go);
    cp16(d + AB + 16,     kl + go + 8);
    cp16(d + 2*AB,        vh + go);
    cp16(d + 2*AB + 16,   vh + go + 8);
    cp16(d + 3*AB,        vl + go);
    cp16(d + 3*AB + 16,   vl + go + 8);
}

__global__ __launch_bounds__(256) void attn_kernel(const int* __restrict__ wl_ptr) {
    extern __shared__ bf16 asm_[];
    uint32_t sb = smem_u32(asm_);

    int tid  = threadIdx.x;
    int w    = tid >> 5;
    int lane = tid & 31;
    int g    = lane >> 2, tg = lane & 3;
    int ln15 = lane & 15;

    int h  = blockIdx.x & 15;
    int b  = blockIdx.x >> 4;
    int q0 = (int)(gridDim.y - 1 - blockIdx.y) * 128;
    int kvh = h >> 2;

    int wl = *wl_ptr;
    if (wl < 0) wl = TT;

    int qr0   = q0 + w * 16 + g;
    int qr1   = qr0 + 8;
    int qrmin = q0 + w * 16;
    int qrmax = qrmin + 15;

    // ---- Q fragments from pre-split g_qh/g_ql ----
    uint32_t aqh[4][4], aql[4][4];
    {
        const bf16* qb0 = g_qh + (size_t)(b * TT + qr0) * CC + h * DD;
        const bf16* qb1 = qb0 + 8 * CC;
        const bf16* lb0 = g_ql + (size_t)(b * TT + qr0) * CC + h * DD;
        const bf16* lb1 = lb0 + 8 * CC;
#pragma unroll
        for (int s = 0; s < 4; s++) {
            int c = 16 * s + 2 * tg;
            aqh[s][0] = *(const uint32_t*)(qb0 + c);
            aqh[s][1] = *(const uint32_t*)(qb1 + c);
            aqh[s][2] = *(const uint32_t*)(qb0 + c + 8);
            aqh[s][3] = *(const uint32_t*)(qb1 + c + 8);
            aql[s][0] = *(const uint32_t*)(lb0 + c);
            aql[s][1] = *(const uint32_t*)(lb1 + c);
            aql[s][2] = *(const uint32_t*)(lb0 + c + 8);
            aql[s][3] = *(const uint32_t*)(lb1 + c + 8);
        }
    }

    float O[8][4];
#pragma unroll
    for (int j = 0; j < 8; j++)
#pragma unroll
        for (int c = 0; c < 4; c++) O[j][c] = 0.f;
    float m0 = -INFINITY, m1 = -INFINITY, l0 = 0.f, l1 = 0.f;

    int lo_b = q0 - wl;
    int kt_lo = (lo_b > 0) ? (lo_b / 64) : 0;
    int kt_hi = (q0 + 127) / 64;

    const bf16* kh = g_kh + (size_t)b * TT * KVD + kvh * DD;
    const bf16* kl = g_kl + (size_t)b * TT * KVD + kvh * DD;
    const bf16* vh = g_vh + (size_t)b * TT * KVD + kvh * DD;
    const bf16* vl = g_vl + (size_t)b * TT * KVD + kvh * DD;

    attn_issue(kh, kl, vh, vl, sb, kt_lo & 1, kt_lo * 64);
    CP_COMMIT();

#pragma unroll 1
    for (int kt = kt_lo; kt <= kt_hi; kt++) {
        int st = kt & 1;
        int k0 = kt * 64;
        if (kt < kt_hi) {
            attn_issue(kh, kl, vh, vl, sb, st ^ 1, k0 + 64);
            CP_COMMIT();
            CP_WAIT1();
        } else {
            CP_WAIT0();
        }
        __syncthreads();

        bool live = !(k0 > qrmax || k0 + 63 < qrmin - wl);
        if (live) {
            const bf16* skh = asm_ + st * ASTG;
            const bf16* skl = skh + AARR;
            uint32_t vh_b = sb + (uint32_t)(st * ASTG + 2 * AARR) * 2;
            uint32_t vl_b = vh_b + AARR * 2;

            // ---- QK^T ----
            float S[8][4];
#pragma unroll
            for (int j = 0; j < 8; j++)
#pragma unroll
                for (int c = 0; c < 4; c++) S[j][c] = 0.f;
#pragma unroll
            for (int s = 0; s < 4; s++) {
#pragma unroll
                for (int j = 0; j < 8; j++) {
                    int rr = (8 * j + g) * ASP;
                    uint32_t ph0 = lds_b32(skh + rr + (8 * s + tg) * 2);
                    uint32_t ph1 = lds_b32(skh + rr + (8 * s + 4 + tg) * 2);
                    uint32_t pl0 = lds_b32(skl + rr + (8 * s + tg) * 2);
                    uint32_t pl1 = lds_b32(skl + rr + (8 * s + 4 + tg) * 2);
                    mma_bf16(S[j], aqh[s][0], aqh[s][1], aqh[s][2], aqh[s][3], ph0, ph1);
                    mma_bf16(S[j], aqh[s][0], aqh[s][1], aqh[s][2], aqh[s][3], pl0, pl1);
                    mma_bf16(S[j], aql[s][0], aql[s][1], aql[s][2], aql[s][3], ph0, ph1);
                }
            }

            // ---- mask + row max ----
            float mc0 = -INFINITY, mc1 = -INFINITY;
#pragma unroll
            for (int j = 0; j < 8; j++) {
                int kj = k0 + 8 * j + 2 * tg;
                if (!(kj     <= qr0 && qr0 - kj     <= wl)) S[j][0] = -INFINITY;
                if (!(kj + 1 <= qr0 && qr0 - kj - 1 <= wl)) S[j][1] = -INFINITY;
                if (!(kj     <= qr1 && qr1 - kj     <= wl)) S[j][2] = -INFINITY;
                if (!(kj + 1 <= qr1 && qr1 - kj - 1 <= wl)) S[j][3] = -INFINITY;
                mc0 = fmaxf(mc0, fmaxf(S[j][0], S[j][1]));
                mc1 = fmaxf(mc1, fmaxf(S[j][2], S[j][3]));
            }
            mc0 = fmaxf(mc0, __shfl_xor_sync(0xffffffffu, mc0, 1));
            mc0 = fmaxf(mc0, __shfl_xor_sync(0xffffffffu, mc0, 2));
            mc1 = fmaxf(mc1, __shfl_xor_sync(0xffffffffu, mc1, 1));
            mc1 = fmaxf(mc1, __shfl_xor_sync(0xffffffffu, mc1, 2));

            // ---- online softmax ----
            if (mc0 > -INFINITY) {
                float mn = fmaxf(m0, mc0);
                float corr = fast_exp2(m0 - mn);
                m0 = mn; l0 *= corr;
                float sum = 0.f;
#pragma unroll
                for (int j = 0; j < 8; j++) {
                    O[j][0] *= corr; O[j][1] *= corr;
                    S[j][0] = fast_exp2(S[j][0] - m0);
                    S[j][1] = fast_exp2(S[j][1] - m0);
                    sum += S[j][0] + S[j][1];
                }
                l0 += sum;
            } else {
#pragma unroll
                for (int j = 0; j < 8; j++) { S[j][0] = 0.f; S[j][1] = 0.f; }
            }
            if (mc1 > -INFINITY) {
                float mn = fmaxf(m1, mc1);
                float corr = fast_exp2(m1 - mn);
                m1 = mn; l1 *= corr;
                float sum = 0.f;
#pragma unroll
                for (int j = 0; j < 8; j++) {
                    O[j][2] *= corr; O[j][3] *= corr;
                    S[j][2] = fast_exp2(S[j][2] - m1);
                    S[j][3] = fast_exp2(S[j][3] - m1);
                    sum += S[j][2] + S[j][3];
                }
                l1 += sum;
            } else {
#pragma unroll
                for (int j = 0; j < 8; j++) { S[j][2] = 0.f; S[j][3] = 0.f; }
            }

            // ---- pack P, PV ----
            uint32_t pah[4][4], pal[4][4];
#pragma unroll
            for (int s = 0; s < 4; s++) {
                split2(S[2*s][0],   S[2*s][1],   pah[s][0], pal[s][0]);
                split2(S[2*s][2],   S[2*s][3],   pah[s][1], pal[s][1]);
                split2(S[2*s+1][0], S[2*s+1][1], pah[s][2], pal[s][2]);
                split2(S[2*s+1][2], S[2*s+1][3], pah[s][3], pal[s][3]);
            }
#pragma unroll
            for (int s = 0; s < 4; s++) {
                uint32_t rowh = vh_b + (16 * s + ln15) * (ASP * 2);
                uint32_t rowl = vl_b + (16 * s + ln15) * (ASP * 2);
#pragma unroll
                for (int j = 0; j < 8; j++) {
                    uint32_t bh0, bh1, bl0, bl1;
                    ldsm_x2_trans(rowh + 16 * j, bh0, bh1);
                    ldsm_x2_trans(rowl + 16 * j, bl0, bl1);
                    mma_bf16(O[j], pah[s][0], pah[s][1], pah[s][2], pah[s][3], bh0, bh1);
                    mma_bf16(O[j], pah[s][0], pah[s][1], pah[s][2], pah[s][3], bl0, bl1);
                    mma_bf16(O[j], pal[s][0], pal[s][1], pal[s][2], pal[s][3], bh0, bh1);
                }
            }
        }
        __syncthreads();
    }

    // ---- epilogue: normalize + split to bf16 hi/lo for proj ----
    l0 += __shfl_xor_sync(0xffffffffu, l0, 1);
    l0 += __shfl_xor_sync(0xffffffffu, l0, 2);
    l1 += __shfl_xor_sync(0xffffffffu, l1, 1);
    l1 += __shfl_xor_sync(0xffffffffu, l1, 2);
    float inv0 = 1.0f / l0;
    float inv1 = 1.0f / l1;
    size_t ro0 = (size_t)(b * TT + qr0) * CC + h * DD;
    size_t ro1 = ro0 + 8 * CC;
#pragma unroll
    for (int j = 0; j < 8; j++) {
        int col = 8 * j + 2 * tg;
        uint32_t ph, pl;
        split2(O[j][0] * inv0, O[j][1] * inv0, ph, pl);
        *(uint32_t*)&g_ah[ro0 + col] = ph;
        *(uint32_t*)&g_al[ro0 + col] = pl;
        split2(O[j][2] * inv1, O[j][3] * inv1, ph, pl);
        *(uint32_t*)&g_ah[ro1 + col] = ph;
        *(uint32_t*)&g_al[ro1 + col] = pl;
    }
}

// ---------------- launch -----------------------------------------------------
extern "C" void kernel_launch(void* const* d_in, const int* in_sizes, int n_in,
                              void* d_out, int out_size) {
    const float* x     = (const float*)d_in[0];
    const float* wq    = (const float*)d_in[1];
    const float* wk    = (const float*)d_in[2];
    const float* wv    = (const float*)d_in[3];
    const float* wproj = (const float*)d_in[4];
    const float* qgain = (const float*)d_in[5];
    const int*   wl    = (const int*)d_in[6];
    float* out = (float*)d_out;

    cudaFuncSetAttribute(qkv_gemm_kernel,
                         cudaFuncAttributeMaxDynamicSharedMemorySize, GEMM_SMEM_BYTES);
    cudaFuncSetAttribute(proj_gemm_kernel,
                         cudaFuncAttributeMaxDynamicSharedMemorySize, GEMM_SMEM_BYTES);
    cudaFuncSetAttribute(attn_kernel,
                         cudaFuncAttributeMaxDynamicSharedMemorySize, ATTN_SMEM_BYTES);

    rope_table_kernel<<<(TT * 8 + 255) / 256, 256>>>();

    const int NQUAD = MM*CC/4 + CC*CC/4 + KVD*CC/4 + KVD*CC/4 + CC*CC/4;
    cvt_all_kernel<<<(NQUAD + 255) / 256, 256>>>(x, wq, wk, wv, wproj);

    dim3 g1(MM / 128, NW / 128);               // 32 x 12
    qkv_gemm_kernel<<<g1, 256, GEMM_SMEM_BYTES>>>();

    int ntask = MM * (HH + HKVV);
    norm_rope_kernel<<<(ntask * 32 + 255) / 256, 256>>>(qgain);

    dim3 g2(HH * BB, TT / 128);                // 32 x 16
    attn_kernel<<<g2, 256, ATTN_SMEM_BYTES>>>(wl);

    dim3 g3(MM / 128, CC / 128);               // 32 x 8
    proj_gemm_kernel<<<g3, 256, GEMM_SMEM_BYTES>>>(out);
}

// round 12
// speedup vs baseline: 4.0357x; 1.0362x over previous
#include <cuda_runtime.h>
#include <cuda_bf16.h>
#include <math.h>
#include <cstdint>

// Problem constants (fixed by setup_inputs)
#define BB   2
#define TT   2048
#define CC   1024
#define HH   16
#define HKVV 4
#define DD   64
#define MM   (BB*TT)          // 4096 rows
#define KVD  (HKVV*DD)        // 256
#define NW   (CC + 2*KVD)     // 1536 fused qkv output rows

typedef __nv_bfloat16  bf16;
typedef __nv_bfloat162 bf162;

// ---------------- scratch (static device globals; no allocs allowed) --------
__device__ float g_q[MM * CC];      // qkv fp32 out (pre-norm)
__device__ float g_k[MM * KVD];
__device__ __align__(128) bf16 g_xh[MM * CC],  g_xl[MM * CC];
__device__ __align__(128) bf16 g_wfh[NW * CC], g_wfl[NW * CC];   // wq|wk|wv fused
__device__ __align__(128) bf16 g_wph[CC * CC], g_wpl[CC * CC];
__device__ __align__(128) bf16 g_qh[MM * CC],  g_ql[MM * CC];    // post norm/rope/scale
__device__ __align__(128) bf16 g_kh[MM * KVD], g_kl[MM * KVD];
__device__ __align__(128) bf16 g_vh[MM * KVD], g_vl[MM * KVD];
__device__ __align__(128) bf16 g_ah[MM * CC],  g_al[MM * CC];    // attention out
__device__ float g_cos[TT][8];
__device__ float g_sin[TT][8];

// ---------------- PTX helpers ------------------------------------------------
__device__ __forceinline__ void mma_bf16(
    float* c, uint32_t a0, uint32_t a1, uint32_t a2, uint32_t a3,
    uint32_t b0, uint32_t b1)
{
    asm volatile(
        "mma.sync.aligned.m16n8k16.row.col.f32.bf16.bf16.f32 "
        "{%0,%1,%2,%3}, {%4,%5,%6,%7}, {%8,%9}, {%0,%1,%2,%3};"
        : "+f"(c[0]), "+f"(c[1]), "+f"(c[2]), "+f"(c[3])
        : "r"(a0), "r"(a1), "r"(a2), "r"(a3), "r"(b0), "r"(b1));
}
__device__ __forceinline__ float fast_exp2(float x) {
    float y; asm("ex2.approx.f32 %0, %1;" : "=f"(y) : "f"(x)); return y;
}
__device__ __forceinline__ uint32_t smem_u32(const void* p) {
    uint32_t a;
    asm("{ .reg .u64 t; cvta.to.shared.u64 t, %1; cvt.u32.u64 %0, t; }"
        : "=r"(a) : "l"(p));
    return a;
}
__device__ __forceinline__ void ldsm_x4(
    uint32_t addr, uint32_t& r0, uint32_t& r1, uint32_t& r2, uint32_t& r3)
{
    asm volatile("ldmatrix.sync.aligned.m8n8.x4.shared.b16 {%0,%1,%2,%3}, [%4];"
                 : "=r"(r0), "=r"(r1), "=r"(r2), "=r"(r3) : "r"(addr));
}
__device__ __forceinline__ void ldsm_x4_t(
    uint32_t addr, uint32_t& r0, uint32_t& r1, uint32_t& r2, uint32_t& r3)
{
    asm volatile("ldmatrix.sync.aligned.m8n8.x4.trans.shared.b16 {%0,%1,%2,%3}, [%4];"
                 : "=r"(r0), "=r"(r1), "=r"(r2), "=r"(r3) : "r"(addr));
}
__device__ __forceinline__ void cp16(uint32_t dst, const void* src) {
    asm volatile("cp.async.cg.shared.global [%0], [%1], 16;" :: "r"(dst), "l"(src));
}
#define CP_COMMIT() asm volatile("cp.async.commit_group;" ::: "memory")
#define CP_WAIT1()  asm volatile("cp.async.wait_group 1;"  ::: "memory")
#define CP_WAIT0()  asm volatile("cp.async.wait_group 0;"  ::: "memory")

// split two fp32 into packed bf16x2 hi + lo(residual)
__device__ __forceinline__ void split2(float x, float y, uint32_t& hi, uint32_t& lo) {
    bf16 hx = __float2bfloat16_rn(x), hy = __float2bfloat16_rn(y);
    bf162 h2 = __halves2bfloat162(hx, hy);
    hi = *(uint32_t*)&h2;
    bf162 l2 = __floats2bfloat162_rn(x - __bfloat162float(hx),
                                     y - __bfloat162float(hy));
    lo = *(uint32_t*)&l2;
}

// ---------------- pre-convert: fp32 -> (hi, lo) bf16 ------------------------
__global__ void cvt_all_kernel(
    const float* __restrict__ x,  const float* __restrict__ wq,
    const float* __restrict__ wk, const float* __restrict__ wv,
    const float* __restrict__ wp)
{
    const int N0 = MM * CC / 4;
    const int N1 = N0 + CC * CC / 4;
    const int N2 = N1 + KVD * CC / 4;
    const int N3 = N2 + KVD * CC / 4;
    const int N4 = N3 + CC * CC / 4;
    int i = blockIdx.x * blockDim.x + threadIdx.x;
    if (i >= N4) return;
    const float* src; bf16* hi; bf16* lo; int q;
    if (i < N0)      { src = x;  hi = g_xh;  lo = g_xl;  q = i; }
    else if (i < N1) { src = wq; hi = g_wfh; lo = g_wfl; q = i - N0; }
    else if (i < N2) { src = wk; hi = g_wfh + (size_t)CC * CC;
                       lo = g_wfl + (size_t)CC * CC;               q = i - N1; }
    else if (i < N3) { src = wv; hi = g_wfh + (size_t)(CC + KVD) * CC;
                       lo = g_wfl + (size_t)(CC + KVD) * CC;       q = i - N2; }
    else             { src = wp; hi = g_wph; lo = g_wpl; q = i - N3; }
    float4 v = ((const float4*)src)[q];
    bf16 hx = __float2bfloat16_rn(v.x), hy = __float2bfloat16_rn(v.y);
    bf16 hz = __float2bfloat16_rn(v.z), hw = __float2bfloat16_rn(v.w);
    ((bf162*)hi)[2*q]   = __halves2bfloat162(hx, hy);
    ((bf162*)hi)[2*q+1] = __halves2bfloat162(hz, hw);
    ((bf162*)lo)[2*q]   = __floats2bfloat162_rn(v.x - __bfloat162float(hx),
                                                v.y - __bfloat162float(hy));
    ((bf162*)lo)[2*q+1] = __floats2bfloat162_rn(v.z - __bfloat162float(hz),
                                                v.w - __bfloat162float(hw));
}

// ---------------- GEMM: pure-bf16 cp.async pipeline + mma.sync + ldmatrix ----
#define SP     40                 // smem row stride (bf16 elems), conflict-free
#define GARR   (128 * SP)         // 5120 elems per array
#define GSTAGE (4 * GARR)         // Ah,Al,Bh,Bl
#define GEMM_SMEM_BYTES (2 * GSTAGE * 2)   // 81920 B (2 stages)

__device__ __forceinline__ void gemm_issue(
    const bf16* Ah, const bf16* Al, const bf16* Bh, const bf16* Bl,
    uint32_t sb, int st, int ch)
{
    int tid = threadIdx.x;
    int r   = tid >> 1;
    int s0  = (tid & 1) * 2;
    size_t go = (size_t)r * CC + ch * 32 + s0 * 8;
    uint32_t d = sb + (uint32_t)(st * GSTAGE + r * SP + s0 * 8) * 2;
    const uint32_t AB = GARR * 2;
    cp16(d,               Ah + go);
    cp16(d + 16,          Ah + go + 8);
    cp16(d + AB,          Al + go);
    cp16(d + AB + 16,     Al + go + 8);
    cp16(d + 2*AB,        Bh + go);
    cp16(d + 2*AB + 16,   Bh + go + 8);
    cp16(d + 3*AB,        Bl + go);
    cp16(d + 3*AB + 16,   Bl + go + 8);
}

// one k16 step: operands via ldmatrix.x4 (layout identical to LDS version)
__device__ __forceinline__ void gemm_compute_k16(
    uint32_t sA, uint32_t sB, uint32_t aoff, uint32_t boff, int kk, float* acc)
{
    const uint32_t LO = GARR * 2;
    uint32_t bfh[8], bfl[8];
#pragma unroll
    for (int jp = 0; jp < 2; jp++) {
        uint32_t ab = sB + boff + (uint32_t)(jp * 16 * SP + kk) * 2;
        ldsm_x4(ab,      bfh[4*jp], bfh[4*jp+1], bfh[4*jp+2], bfh[4*jp+3]);
        ldsm_x4(ab + LO, bfl[4*jp], bfl[4*jp+1], bfl[4*jp+2], bfl[4*jp+3]);
    }
#pragma unroll
    for (int i = 0; i < 4; i++) {
        uint32_t aa = sA + aoff + (uint32_t)(i * 16 * SP + kk) * 2;
        uint32_t a0, a1, a2, a3, l0, l1, l2, l3;
        ldsm_x4(aa,      a0, a1, a2, a3);
        ldsm_x4(aa + LO, l0, l1, l2, l3);
#pragma unroll
        for (int j = 0; j < 4; j++) {
            float* c = acc + (i*4 + j) * 4;
            mma_bf16(c, a0, a1, a2, a3, bfh[2*j], bfh[2*j+1]);
            mma_bf16(c, a0, a1, a2, a3, bfl[2*j], bfl[2*j+1]);
            mma_bf16(c, l0, l1, l2, l3, bfh[2*j], bfh[2*j+1]);
        }
    }
}

// Y tile = A[128,1024] @ B[128,1024]^T; operands pre-offset to tile origin.
__device__ __forceinline__ void bf16_gemm_body(
    const bf16* Ah, const bf16* Al, const bf16* Bh, const bf16* Bl,
    float* Y, int ldy, int m0, int n0y, int vout)
{
    extern __shared__ bf16 gsm[];
    uint32_t sb = smem_u32(gsm);
    int tid = threadIdx.x, wid = tid >> 5, lane = tid & 31;
    int g = lane >> 2, tg = lane & 3;
    int mbase = (wid & 1) * 64;
    int nbase = (wid >> 1) * 32;

    // ldmatrix lane address offsets (bytes), layout identical to LDS version
    uint32_t aoff = (uint32_t)((mbase + (lane & 15)) * SP + ((lane >> 4) & 1) * 8) * 2;
    uint32_t boff = (uint32_t)((nbase + (lane & 7) + ((lane & 16) ? 8 : 0)) * SP
                               + ((lane & 8) ? 8 : 0)) * 2;

    float acc[64];
#pragma unroll
    for (int i = 0; i < 64; i++) acc[i] = 0.f;

    gemm_issue(Ah, Al, Bh, Bl, sb, 0, 0);
    CP_COMMIT();

#pragma unroll 1
    for (int ch = 0; ch < 32; ch++) {
        int st = ch & 1;
        if (ch < 31) {
            gemm_issue(Ah, Al, Bh, Bl, sb, st ^ 1, ch + 1);
            CP_COMMIT();
            CP_WAIT1();
        } else {
            CP_WAIT0();
        }
        __syncthreads();
        uint32_t sA = sb + (uint32_t)(st * GSTAGE) * 2;
        uint32_t sB = sA + 2 * GARR * 2;
        gemm_compute_k16(sA, sB, aoff, boff, 0, acc);
        gemm_compute_k16(sA, sB, aoff, boff, 16, acc);
        __syncthreads();
    }

#pragma unroll
    for (int i = 0; i < 4; i++) {
#pragma unroll
        for (int j = 0; j < 4; j++) {
            float* c = acc + (i*4 + j) * 4;
            int mrow = m0 + mbase + i*16 + g;
            int ncol = n0y + nbase + j*8 + tg*2;
            if (!vout) {
                *(float2*)&Y[(size_t)mrow * ldy + ncol]       = make_float2(c[0], c[1]);
                *(float2*)&Y[(size_t)(mrow + 8) * ldy + ncol] = make_float2(c[2], c[3]);
            } else {
                uint32_t ph, pl;
                split2(c[0], c[1], ph, pl);
                *(uint32_t*)&g_vh[(size_t)mrow * KVD + ncol] = ph;
                *(uint32_t*)&g_vl[(size_t)mrow * KVD + ncol] = pl;
                split2(c[2], c[3], ph, pl);
                *(uint32_t*)&g_vh[(size_t)(mrow + 8) * KVD + ncol] = ph;
                *(uint32_t*)&g_vl[(size_t)(mrow + 8) * KVD + ncol] = pl;
            }
        }
    }
}

__global__ __launch_bounds__(256, 2) void qkv_gemm_kernel() {
    int m0 = blockIdx.x * 128;
    int n0 = blockIdx.y * 128;
    const bf16* Ah = g_xh + (size_t)m0 * CC;
    const bf16* Al = g_xl + (size_t)m0 * CC;
    const bf16* Bh = g_wfh + (size_t)n0 * CC;
    const bf16* Bl = g_wfl + (size_t)n0 * CC;
    if (n0 < CC)
        bf16_gemm_body(Ah, Al, Bh, Bl, g_q, CC, m0, n0, 0);
    else if (n0 < CC + KVD)
        bf16_gemm_body(Ah, Al, Bh, Bl, g_k, KVD, m0, n0 - CC, 0);
    else
        bf16_gemm_body(Ah, Al, Bh, Bl, nullptr, KVD, m0, n0 - CC - KVD, 1);
}

__global__ __launch_bounds__(256, 2) void proj_gemm_kernel(float* __restrict__ out) {
    int m0 = blockIdx.x * 128;
    int n0 = blockIdx.y * 128;
    bf16_gemm_body(g_ah + (size_t)m0 * CC, g_al + (size_t)m0 * CC,
                   g_wph + (size_t)n0 * CC, g_wpl + (size_t)n0 * CC,
                   out, CC, m0, n0, 0);
}

// ---------------- RoPE table (double precision of fp32 angle) ---------------
__global__ void rope_table_kernel() {
    int idx = blockIdx.x * blockDim.x + threadIdx.x;
    if (idx >= TT * 8) return;
    int t = idx >> 3;
    int i = idx & 7;
    double inv_d = exp2(-((double)(2 * i) / 64.0) * 13.28771237954945);
    float inv_f = (float)inv_d;
    float ang = (float)t * inv_f;
    g_cos[t][i] = (float)cos((double)ang);
    g_sin[t][i] = (float)sin((double)ang);
}

// ---- RMS norm + partial RoPE (+qscale for q) -> bf16 hi/lo -----------------
__global__ void norm_rope_kernel(const float* __restrict__ qgain) {
    int gtid = blockIdx.x * blockDim.x + threadIdx.x;
    int task = gtid >> 5;
    int lane = gtid & 31;
    const int NTASK = MM * (HH + HKVV);
    if (task >= NTASK) return;
    int row = task / (HH + HKVV);
    int hh  = task % (HH + HKVV);
    const float* base = (hh < HH) ? (g_q + (size_t)row * CC + hh * DD)
                                  : (g_k + (size_t)row * KVD + (hh - HH) * DD);
    float v0 = base[lane];
    float v1 = base[lane + 32];
    float ss = v0 * v0 + v1 * v1;
#pragma unroll
    for (int o = 16; o; o >>= 1) ss += __shfl_xor_sync(0xffffffffu, ss, o);
    float a = ss * (1.0f / 64.0f) + 1.1920929e-07f;
    float r = rsqrtf(a);
    r = r * (1.5f - 0.5f * a * r * r);
    v0 *= r; v1 *= r;
    int t = row % TT;
    float p = __shfl_xor_sync(0xffffffffu, v0, 8);
    if (lane < 16) {
        int i = lane & 7;
        float c = g_cos[t][i], s = g_sin[t][i];
        v0 = (lane < 8) ? (v0 * c + p * s) : (v0 * c - p * s);
    }
    if (hh < HH) {
        float qsc = qgain[hh] * 0.125f * 1.4426950408889634f;
        v0 *= qsc; v1 *= qsc;
        size_t o = (size_t)row * CC + hh * DD + lane;
        bf16 h0 = __float2bfloat16_rn(v0);
        bf16 h1 = __float2bfloat16_rn(v1);
        g_qh[o]      = h0; g_ql[o]      = __float2bfloat16_rn(v0 - __bfloat162float(h0));
        g_qh[o + 32] = h1; g_ql[o + 32] = __float2bfloat16_rn(v1 - __bfloat162float(h1));
    } else {
        size_t o = (size_t)row * KVD + (hh - HH) * DD + lane;
        bf16 h0 = __float2bfloat16_rn(v0);
        bf16 h1 = __float2bfloat16_rn(v1);
        g_kh[o]      = h0; g_kl[o]      = __float2bfloat16_rn(v0 - __bfloat162float(h0));
        g_kh[o + 32] = h1; g_kl[o + 32] = __float2bfloat16_rn(v1 - __bfloat162float(h1));
    }
}

// ---------------- flash attention (mma.sync, pre-split, ldmatrix) ------------
#define ASP  72                    // smem row stride (bf16 elems)
#define AARR (64 * ASP)            // 4608 elems
#define ASTG (4 * AARR)            // Kh,Kl,Vh,Vl
#define ATTN_SMEM_BYTES (2 * ASTG * 2)   // 73728 B

__device__ __forceinline__ void attn_issue(
    const bf16* kh, const bf16* kl, const bf16* vh, const bf16* vl,
    uint32_t sb, int st, int k0)
{
    int tid = threadIdx.x;
    int r   = tid >> 2;                  // key row 0..63
    int s0  = (tid & 3) * 2;             // segs s0, s0+1 (of 8)
    size_t go = (size_t)(k0 + r) * KVD + s0 * 8;
    uint32_t d = sb + (uint32_t)(st * ASTG + r * ASP + s0 * 8) * 2;
    const uint32_t AB = AARR * 2;
    cp16(d,               kh + go);
    cp16(d + 16,          kh + go + 8);
    cp16(d + AB,          kl + go);
    cp16(d + AB + 16,     kl + go + 8);
    cp16(d + 2*AB,        vh + go);
    cp16(d + 2*AB + 16,   vh + go + 8);
    cp16(d + 3*AB,        vl + go);
    cp16(d + 3*AB + 16,   vl + go + 8);
}

__global__ __launch_bounds__(256) void attn_kernel(const int* __restrict__ wl_ptr) {
    extern __shared__ bf16 asm_[];
    uint32_t sb = smem_u32(asm_);

    int tid  = threadIdx.x;
    int w    = tid >> 5;
    int lane = tid & 31;
    int g    = lane >> 2, tg = lane & 3;
    int ln15 = lane & 15;

    int h  = blockIdx.x & 15;
    int b  = blockIdx.x >> 4;
    int q0 = (int)(gridDim.y - 1 - blockIdx.y) * 128;
    int kvh = h >> 2;

    int wl = *wl_ptr;
    if (wl < 0) wl = TT;

    int qr0   = q0 + w * 16 + g;
    int qr1   = qr0 + 8;
    int qrmin = q0 + w * 16;
    int qrmax = qrmin + 15;

    // K ldmatrix lane offset (bytes): n=(lane&7)+((lane&16)?8:0), k-col=(lane&8)?8:0
    uint32_t koff = (uint32_t)(((lane & 7) + ((lane & 16) ? 8 : 0)) * ASP
                               + ((lane & 8) ? 8 : 0)) * 2;

    // ---- Q fragments from pre-split g_qh/g_ql ----
    uint32_t aqh[4][4], aql[4][4];
    {
        const bf16* qb0 = g_qh + (size_t)(b * TT + qr0) * CC + h * DD;
        const bf16* qb1 = qb0 + 8 * CC;
        const bf16* lb0 = g_ql + (size_t)(b * TT + qr0) * CC + h * DD;
        const bf16* lb1 = lb0 + 8 * CC;
#pragma unroll
        for (int s = 0; s < 4; s++) {
            int c = 16 * s + 2 * tg;
            aqh[s][0] = *(const uint32_t*)(qb0 + c);
            aqh[s][1] = *(const uint32_t*)(qb1 + c);
            aqh[s][2] = *(const uint32_t*)(qb0 + c + 8);
            aqh[s][3] = *(const uint32_t*)(qb1 + c + 8);
            aql[s][0] = *(const uint32_t*)(lb0 + c);
            aql[s][1] = *(const uint32_t*)(lb1 + c);
            aql[s][2] = *(const uint32_t*)(lb0 + c + 8);
            aql[s][3] = *(const uint32_t*)(lb1 + c + 8);
        }
    }

    float O[8][4];
#pragma unroll
    for (int j = 0; j < 8; j++)
#pragma unroll
        for (int c = 0; c < 4; c++) O[j][c] = 0.f;
    float m0 = -INFINITY, m1 = -INFINITY, l0 = 0.f, l1 = 0.f;

    int lo_b = q0 - wl;
    int kt_lo = (lo_b > 0) ? (lo_b / 64) : 0;
    int kt_hi = (q0 + 127) / 64;

    const bf16* kh = g_kh + (size_t)b * TT * KVD + kvh * DD;
    const bf16* kl = g_kl + (size_t)b * TT * KVD + kvh * DD;
    const bf16* vh = g_vh + (size_t)b * TT * KVD + kvh * DD;
    const bf16* vl = g_vl + (size_t)b * TT * KVD + kvh * DD;

    attn_issue(kh, kl, vh, vl, sb, kt_lo & 1, kt_lo * 64);
    CP_COMMIT();

#pragma unroll 1
    for (int kt = kt_lo; kt <= kt_hi; kt++) {
        int st = kt & 1;
        int k0 = kt * 64;
        if (kt < kt_hi) {
            attn_issue(kh, kl, vh, vl, sb, st ^ 1, k0 + 64);
            CP_COMMIT();
            CP_WAIT1();
        } else {
            CP_WAIT0();
        }
        __syncthreads();

        bool live = !(k0 > qrmax || k0 + 63 < qrmin - wl);
        if (live) {
            uint32_t skh_a = sb + (uint32_t)(st * ASTG) * 2;           // Kh
            uint32_t vh_b  = sb + (uint32_t)(st * ASTG + 2 * AARR) * 2; // Vh
            const uint32_t ALO = AARR * 2;

            // ---- QK^T (K frags via ldmatrix.x4) ----
            float S[8][4];
#pragma unroll
            for (int j = 0; j < 8; j++)
#pragma unroll
                for (int c = 0; c < 4; c++) S[j][c] = 0.f;
#pragma unroll
            for (int s = 0; s < 4; s++) {
                uint32_t kk2 = (uint32_t)(s * 16) * 2;
#pragma unroll
                for (int jp = 0; jp < 4; jp++) {
                    uint32_t ab = skh_a + koff + (uint32_t)(jp * 16 * ASP) * 2 + kk2;
                    uint32_t h0, h1, h2, h3, e0, e1, e2, e3;
                    ldsm_x4(ab,       h0, h1, h2, h3);
                    ldsm_x4(ab + ALO, e0, e1, e2, e3);
                    mma_bf16(S[2*jp],   aqh[s][0], aqh[s][1], aqh[s][2], aqh[s][3], h0, h1);
                    mma_bf16(S[2*jp],   aqh[s][0], aqh[s][1], aqh[s][2], aqh[s][3], e0, e1);
                    mma_bf16(S[2*jp],   aql[s][0], aql[s][1], aql[s][2], aql[s][3], h0, h1);
                    mma_bf16(S[2*jp+1], aqh[s][0], aqh[s][1], aqh[s][2], aqh[s][3], h2, h3);
                    mma_bf16(S[2*jp+1], aqh[s][0], aqh[s][1], aqh[s][2], aqh[s][3], e2, e3);
                    mma_bf16(S[2*jp+1], aql[s][0], aql[s][1], aql[s][2], aql[s][3], h2, h3);
                }
            }

            // ---- mask + row max ----
            float mc0 = -INFINITY, mc1 = -INFINITY;
#pragma unroll
            for (int j = 0; j < 8; j++) {
                int kj = k0 + 8 * j + 2 * tg;
                if (!(kj     <= qr0 && qr0 - kj     <= wl)) S[j][0] = -INFINITY;
                if (!(kj + 1 <= qr0 && qr0 - kj - 1 <= wl)) S[j][1] = -INFINITY;
                if (!(kj     <= qr1 && qr1 - kj     <= wl)) S[j][2] = -INFINITY;
                if (!(kj + 1 <= qr1 && qr1 - kj - 1 <= wl)) S[j][3] = -INFINITY;
                mc0 = fmaxf(mc0, fmaxf(S[j][0], S[j][1]));
                mc1 = fmaxf(mc1, fmaxf(S[j][2], S[j][3]));
            }
            mc0 = fmaxf(mc0, __shfl_xor_sync(0xffffffffu, mc0, 1));
            mc0 = fmaxf(mc0, __shfl_xor_sync(0xffffffffu, mc0, 2));
            mc1 = fmaxf(mc1, __shfl_xor_sync(0xffffffffu, mc1, 1));
            mc1 = fmaxf(mc1, __shfl_xor_sync(0xffffffffu, mc1, 2));

            // ---- online softmax ----
            if (mc0 > -INFINITY) {
                float mn = fmaxf(m0, mc0);
                float corr = fast_exp2(m0 - mn);
                m0 = mn; l0 *= corr;
                float sum = 0.f;
#pragma unroll
                for (int j = 0; j < 8; j++) {
                    O[j][0] *= corr; O[j][1] *= corr;
                    S[j][0] = fast_exp2(S[j][0] - m0);
                    S[j][1] = fast_exp2(S[j][1] - m0);
                    sum += S[j][0] + S[j][1];
                }
                l0 += sum;
            } else {
#pragma unroll
                for (int j = 0; j < 8; j++) { S[j][0] = 0.f; S[j][1] = 0.f; }
            }
            if (mc1 > -INFINITY) {
                float mn = fmaxf(m1, mc1);
                float corr = fast_exp2(m1 - mn);
                m1 = mn; l1 *= corr;
                float sum = 0.f;
#pragma unroll
                for (int j = 0; j < 8; j++) {
                    O[j][2] *= corr; O[j][3] *= corr;
                    S[j][2] = fast_exp2(S[j][2] - m1);
                    S[j][3] = fast_exp2(S[j][3] - m1);
                    sum += S[j][2] + S[j][3];
                }
                l1 += sum;
            } else {
#pragma unroll
                for (int j = 0; j < 8; j++) { S[j][2] = 0.f; S[j][3] = 0.f; }
            }

            // ---- pack P, PV (V frags via ldmatrix.x4.trans) ----
            uint32_t pah[4][4], pal[4][4];
#pragma unroll
            for (int s = 0; s < 4; s++) {
                split2(S[2*s][0],   S[2*s][1],   pah[s][0], pal[s][0]);
                split2(S[2*s][2],   S[2*s][3],   pah[s][1], pal[s][1]);
                split2(S[2*s+1][0], S[2*s+1][1], pah[s][2], pal[s][2]);
                split2(S[2*s+1][2], S[2*s+1][3], pah[s][3], pal[s][3]);
            }
#pragma unroll
            for (int s = 0; s < 4; s++) {
                uint32_t rowh4 = vh_b + (uint32_t)((16 * s + ln15) * (ASP * 2))
                               + ((uint32_t)(lane >> 4) << 4);
#pragma unroll
                for (int j = 0; j < 8; j += 2) {
                    uint32_t bh0, bh1, bh2, bh3, bl0, bl1, bl2, bl3;
                    ldsm_x4_t(rowh4 + 16 * j,       bh0, bh1, bh2, bh3);
                    ldsm_x4_t(rowh4 + ALO + 16 * j, bl0, bl1, bl2, bl3);
                    mma_bf16(O[j],   pah[s][0], pah[s][1], pah[s][2], pah[s][3], bh0, bh1);
                    mma_bf16(O[j],   pah[s][0], pah[s][1], pah[s][2], pah[s][3], bl0, bl1);
                    mma_bf16(O[j],   pal[s][0], pal[s][1], pal[s][2], pal[s][3], bh0, bh1);
                    mma_bf16(O[j+1], pah[s][0], pah[s][1], pah[s][2], pah[s][3], bh2, bh3);
                    mma_bf16(O[j+1], pah[s][0], pah[s][1], pah[s][2], pah[s][3], bl2, bl3);
                    mma_bf16(O[j+1], pal[s][0], pal[s][1], pal[s][2], pal[s][3], bh2, bh3);
                }
            }
        }
        __syncthreads();
    }

    // ---- epilogue: normalize + split to bf16 hi/lo for proj ----
    l0 += __shfl_xor_sync(0xffffffffu, l0, 1);
    l0 += __shfl_xor_sync(0xffffffffu, l0, 2);
    l1 += __shfl_xor_sync(0xffffffffu, l1, 1);
    l1 += __shfl_xor_sync(0xffffffffu, l1, 2);
    float inv0 = 1.0f / l0;
    float inv1 = 1.0f / l1;
    size_t ro0 = (size_t)(b * TT + qr0) * CC + h * DD;
    size_t ro1 = ro0 + 8 * CC;
#pragma unroll
    for (int j = 0; j < 8; j++) {
        int col = 8 * j + 2 * tg;
        uint32_t ph, pl;
        split2(O[j][0] * inv0, O[j][1] * inv0, ph, pl);
        *(uint32_t*)&g_ah[ro0 + col] = ph;
        *(uint32_t*)&g_al[ro0 + col] = pl;
        split2(O[j][2] * inv1, O[j][3] * inv1, ph, pl);
        *(uint32_t*)&g_ah[ro1 + col] = ph;
        *(uint32_t*)&g_al[ro1 + col] = pl;
    }
}

// ---------------- launch -----------------------------------------------------
extern "C" void kernel_launch(void* const* d_in, const int* in_sizes, int n_in,
                              void* d_out, int out_size) {
    const float* x     = (const float*)d_in[0];
    const float* wq    = (const float*)d_in[1];
    const float* wk    = (const float*)d_in[2];
    const float* wv    = (const float*)d_in[3];
    const float* wproj = (const float*)d_in[4];
    const float* qgain = (const float*)d_in[5];
    const int*   wl    = (const int*)d_in[6];
    float* out = (float*)d_out;

    cudaFuncSetAttribute(qkv_gemm_kernel,
                         cudaFuncAttributeMaxDynamicSharedMemorySize, GEMM_SMEM_BYTES);
    cudaFuncSetAttribute(proj_gemm_kernel,
                         cudaFuncAttributeMaxDynamicSharedMemorySize, GEMM_SMEM_BYTES);
    cudaFuncSetAttribute(attn_kernel,
                         cudaFuncAttributeMaxDynamicSharedMemorySize, ATTN_SMEM_BYTES);

    rope_table_kernel<<<(TT * 8 + 255) / 256, 256>>>();

    const int NQUAD = MM*CC/4 + CC*CC/4 + KVD*CC/4 + KVD*CC/4 + CC*CC/4;
    cvt_all_kernel<<<(NQUAD + 255) / 256, 256>>>(x, wq, wk, wv, wproj);

    dim3 g1(MM / 128, NW / 128);               // 32 x 12
    qkv_gemm_kernel<<<g1, 256, GEMM_SMEM_BYTES>>>();

    int ntask = MM * (HH + HKVV);
    norm_rope_kernel<<<(ntask * 32 + 255) / 256, 256>>>(qgain);

    dim3 g2(HH * BB, TT / 128);                // 32 x 16
    attn_kernel<<<g2, 256, ATTN_SMEM_BYTES>>>(wl);

    dim3 g3(MM / 128, CC / 128);               // 32 x 8
    proj_gemm_kernel<<<g3, 256, GEMM_SMEM_BYTES>>>(out);
}